// round 4
// baseline (speedup 1.0000x reference)
#include <cuda_runtime.h>
#include <math_constants.h>

#define NMAX 50000
#define EMAX 800000
#define FIN 128
#define NHEAD 4
#define HF 256   // NHEAD * F_OUT

// ---- scratch (device globals; no allocation allowed) ----
__device__ float d_ft[NMAX * HF];          // projected features [N,256]
__device__ int   d_ssrc[EMAX];             // src id, CSR (dst-sorted) order
__device__ int   d_deg[NMAX];              // degree histogram
__device__ int   d_off[NMAX + 1];          // CSR offsets
__device__ int   d_cur[NMAX];              // scatter cursors
__device__ int   d_bsum[256];              // scan block sums
__device__ int   d_bpre[256];              // scan block prefixes
__device__ float d_el2[NMAX * NHEAD];
__device__ float d_er2[NMAX * NHEAD];
__device__ float d_w[NHEAD * FIN];         // al*ar - 2*al1*ar1
__device__ float d_wl1[NHEAD * FIN];       // al1^2
__device__ float d_wr1[NHEAD * FIN];       // ar1^2

__device__ __forceinline__ float sel4(const float a[4], int l) {
    return l == 0 ? a[0] : l == 1 ? a[1] : l == 2 ? a[2] : a[3];
}

// packed f32x2 helpers (FFMA2 — only reachable via PTX)
__device__ __forceinline__ unsigned long long pk2(float lo, float hi) {
    unsigned long long r;
    asm("mov.b64 %0, {%1,%2};" : "=l"(r) : "f"(lo), "f"(hi));
    return r;
}
__device__ __forceinline__ void upk2(unsigned long long v, float& lo, float& hi) {
    asm("mov.b64 {%0,%1}, %2;" : "=f"(lo), "=f"(hi) : "l"(v));
}
__device__ __forceinline__ void ffma2(unsigned long long& d, unsigned long long a,
                                      unsigned long long b) {
    asm("fma.rn.f32x2 %0, %1, %2, %0;" : "+l"(d) : "l"(a), "l"(b));
}

// ---- K0: zero degree histogram + combine attention vectors ----
__global__ void kinit(const float* __restrict__ al, const float* __restrict__ ar,
                      const float* __restrict__ al1, const float* __restrict__ ar1, int n) {
    int i = blockIdx.x * 256 + threadIdx.x;
    if (i < n) d_deg[i] = 0;
    if (i < NHEAD * FIN) {
        d_w[i]   = al[i] * ar[i] - 2.0f * al1[i] * ar1[i];
        d_wl1[i] = al1[i] * al1[i];
        d_wr1[i] = ar1[i] * ar1[i];
    }
}

// ---- histogram of dst ----
__global__ void khist(const int* __restrict__ dst, int e) {
    int i = blockIdx.x * blockDim.x + threadIdx.x;
    if (i < e) atomicAdd(&d_deg[dst[i]], 1);
}

// ---- scan A: per-block sums of 256 degrees ----
__global__ void kscanA(int n) {
    __shared__ int sh[256];
    int t = threadIdx.x;
    int i = blockIdx.x * 256 + t;
    sh[t] = (i < n) ? d_deg[i] : 0;
    __syncthreads();
#pragma unroll
    for (int off = 128; off; off >>= 1) {
        if (t < off) sh[t] += sh[t + off];
        __syncthreads();
    }
    if (t == 0) d_bsum[blockIdx.x] = sh[0];
}

// ---- scan B: exclusive scan of block sums (nb <= 256) ----
__global__ void kscanB(int nb, int n, int e) {
    __shared__ int sh[256];
    int t = threadIdx.x;
    sh[t] = (t < nb) ? d_bsum[t] : 0;
    __syncthreads();
#pragma unroll
    for (int off = 1; off < 256; off <<= 1) {
        int x = (t >= off) ? sh[t - off] : 0;
        __syncthreads();
        sh[t] += x;
        __syncthreads();
    }
    if (t < nb) d_bpre[t] = (t ? sh[t - 1] : 0);
    if (t == 0) d_off[n] = e;
}

// ---- scan C: per-block exclusive scan + prefix -> offsets ----
__global__ void kscanC(int n) {
    __shared__ int sh[256];
    int t = threadIdx.x;
    int i = blockIdx.x * 256 + t;
    int v = (i < n) ? d_deg[i] : 0;
    sh[t] = v;
    __syncthreads();
#pragma unroll
    for (int off = 1; off < 256; off <<= 1) {
        int x = (t >= off) ? sh[t - off] : 0;
        __syncthreads();
        sh[t] += x;
        __syncthreads();
    }
    if (i < n) {
        int o = d_bpre[blockIdx.x] + sh[t] - v;  // exclusive
        d_off[i] = o;
        d_cur[i] = o;
    }
}

// ---- scatter src ids into CSR order ----
__global__ void kscatter(const int* __restrict__ src, const int* __restrict__ dst, int e) {
    int i = blockIdx.x * blockDim.x + threadIdx.x;
    if (i < e) {
        int pos = atomicAdd(&d_cur[dst[i]], 1);
        d_ssrc[pos] = src[i];
    }
}

// ---- K2: per-node el2/er2. One warp per node. ----
__global__ void k2_node(const float* __restrict__ feat, int n) {
    __shared__ float wl[NHEAD * FIN], wr[NHEAD * FIN];
    int t = threadIdx.x;
    wl[t] = d_wl1[t]; wl[t + 256] = d_wl1[t + 256];
    wr[t] = d_wr1[t]; wr[t + 256] = d_wr1[t + 256];
    __syncthreads();
    int warp = t >> 5, lane = t & 31;
    int node = blockIdx.x * 8 + warp;
    if (node >= n) return;

    float4 f = *(const float4*)(feat + (size_t)node * FIN + lane * 4);
    float4 f2 = make_float4(f.x * f.x, f.y * f.y, f.z * f.z, f.w * f.w);
    float accl[4], accr[4];
#pragma unroll
    for (int h = 0; h < 4; h++) {
        const float* a = wl + h * FIN + lane * 4;
        const float* b = wr + h * FIN + lane * 4;
        accl[h] = f2.x * a[0] + f2.y * a[1] + f2.z * a[2] + f2.w * a[3];
        accr[h] = f2.x * b[0] + f2.y * b[1] + f2.z * b[2] + f2.w * b[3];
    }
#pragma unroll
    for (int off = 16; off; off >>= 1) {
#pragma unroll
        for (int h = 0; h < 4; h++) {
            accl[h] += __shfl_xor_sync(0xffffffffu, accl[h], off);
            accr[h] += __shfl_xor_sync(0xffffffffu, accr[h], off);
        }
    }
    if (lane < 4) {
        int idx = node * 4 + lane;
        d_el2[idx] = sel4(accl, lane);
        d_er2[idx] = sel4(accr, lane);
    }
}

// ---- K1: ft = feat @ fc_w^T. 64x256 block tile, 8x8 thread tile, FFMA2. ----
__global__ void __launch_bounds__(256) k1_gemm(const float* __restrict__ feat,
                                               const float* __restrict__ fcw, int n) {
    __shared__ float As[64 * 16];    // 4 KB
    __shared__ float Bs[16 * 256];   // 16 KB
    int t = threadIdx.x;
    int tx = t & 31, ty = t >> 5;
    int m0 = blockIdx.x * 64;

    unsigned long long acc2[8][4];
#pragma unroll
    for (int i = 0; i < 8; i++)
#pragma unroll
        for (int j = 0; j < 4; j++) acc2[i][j] = 0ull;

    int arow = t >> 2, akq = (t & 3) * 4;

#pragma unroll
    for (int kc = 0; kc < FIN; kc += 16) {
        float4 av = make_float4(0.f, 0.f, 0.f, 0.f);
        if (m0 + arow < n)
            av = *(const float4*)(feat + (size_t)(m0 + arow) * FIN + kc + akq);
        *(float4*)(As + arow * 16 + akq) = av;
#pragma unroll
        for (int q = 0; q < 4; q++) {
            float4 w4 = *(const float4*)(fcw + (size_t)t * FIN + kc + q * 4);
            Bs[(q * 4 + 0) * 256 + t] = w4.x;
            Bs[(q * 4 + 1) * 256 + t] = w4.y;
            Bs[(q * 4 + 2) * 256 + t] = w4.z;
            Bs[(q * 4 + 3) * 256 + t] = w4.w;
        }
        __syncthreads();

#pragma unroll
        for (int k = 0; k < 16; k++) {
            float4 b0 = *(float4*)&Bs[k * 256 + tx * 8];
            float4 b1 = *(float4*)&Bs[k * 256 + tx * 8 + 4];
            unsigned long long bb0 = pk2(b0.x, b0.y), bb1 = pk2(b0.z, b0.w);
            unsigned long long bb2 = pk2(b1.x, b1.y), bb3 = pk2(b1.z, b1.w);
#pragma unroll
            for (int i = 0; i < 8; i++) {
                float a = As[(ty * 8 + i) * 16 + k];
                unsigned long long aa = pk2(a, a);
                ffma2(acc2[i][0], aa, bb0);
                ffma2(acc2[i][1], aa, bb1);
                ffma2(acc2[i][2], aa, bb2);
                ffma2(acc2[i][3], aa, bb3);
            }
        }
        __syncthreads();
    }

#pragma unroll
    for (int i = 0; i < 8; i++) {
        int row = m0 + ty * 8 + i;
        if (row < n) {
            float4 v0, v1;
            upk2(acc2[i][0], v0.x, v0.y); upk2(acc2[i][1], v0.z, v0.w);
            upk2(acc2[i][2], v1.x, v1.y); upk2(acc2[i][3], v1.z, v1.w);
            float* o = d_ft + (size_t)row * HF + tx * 8;
            *(float4*)o = v0;
            *(float4*)(o + 4) = v1;
        }
    }
}

// ---- K34: fused score + online softmax + aggregation. One block per dst node. ----
__global__ void __launch_bounds__(256) k34_node(const float* __restrict__ feat,
                                                float* __restrict__ out,
                                                const float* __restrict__ bias) {
    __shared__ float ws[NHEAD * FIN];   // 2 KB
    __shared__ float fdS[FIN];          // 512 B
    __shared__ float er2d[4];
    __shared__ float sc[256];           // [h][64] chunk scores
    __shared__ float alphaSm[256];      // [h][64]
    __shared__ int   srcSm[64];
    __shared__ float run_m[4], run_d[4], scaleS[4];

    int node = blockIdx.x;
    int t = threadIdx.x;
    int st = d_off[node];
    int deg = d_off[node + 1] - st;

    if (deg == 0) {
        out[(size_t)node * HF + t] = bias[t];
        return;
    }

    ws[t] = d_w[t]; ws[t + 256] = d_w[t + 256];
    if (t < FIN) fdS[t] = feat[(size_t)node * FIN + t];
    if (t < 4) { er2d[t] = d_er2[node * 4 + t]; run_m[t] = -CUDART_INF_F; run_d[t] = 0.f; }
    __syncthreads();

    int warp = t >> 5, lane = t & 31;
    int h = t >> 6;
    float acc = 0.f;

    for (int c0 = 0; c0 < deg; c0 += 64) {
        int cd = min(64, deg - c0);

        // --- score phase: warp per edge, stride 8 ---
        for (int i = warp; i < cd; i += 8) {
            int s = d_ssrc[st + c0 + i];
            float4 fsv = *(const float4*)(feat + (size_t)s * FIN + lane * 4);
            float4 fdv = *(const float4*)(fdS + lane * 4);
            float4 p = make_float4(fsv.x * fdv.x, fsv.y * fdv.y,
                                   fsv.z * fdv.z, fsv.w * fdv.w);
            float a[4];
#pragma unroll
            for (int hh = 0; hh < 4; hh++) {
                const float* w4 = ws + hh * FIN + lane * 4;
                a[hh] = p.x * w4[0] + p.y * w4[1] + p.z * w4[2] + p.w * w4[3];
            }
#pragma unroll
            for (int off = 16; off; off >>= 1)
#pragma unroll
                for (int hh = 0; hh < 4; hh++)
                    a[hh] += __shfl_xor_sync(0xffffffffu, a[hh], off);
            if (lane < 4)
                sc[lane * 64 + i] = sel4(a, lane) + d_el2[s * 4 + lane] + er2d[lane];
            if (lane == 4) srcSm[i] = s;
        }
        __syncthreads();

        // --- chunk stats + online update: warp per head ---
        if (warp < 4) {
            float cm = -CUDART_INF_F;
            for (int i = lane; i < cd; i += 32) cm = fmaxf(cm, sc[warp * 64 + i]);
#pragma unroll
            for (int off = 16; off; off >>= 1)
                cm = fmaxf(cm, __shfl_xor_sync(0xffffffffu, cm, off));
            float cs = 0.f;
            for (int i = lane; i < cd; i += 32) cs += __expf(sc[warp * 64 + i] - cm);
#pragma unroll
            for (int off = 16; off; off >>= 1)
                cs += __shfl_xor_sync(0xffffffffu, cs, off);
            if (lane == 0) {
                float nm = fmaxf(run_m[warp], cm);
                float so = __expf(run_m[warp] - nm);   // 0 on first chunk
                run_d[warp] = run_d[warp] * so + __expf(cm - nm) * cs;
                scaleS[warp] = so;
                run_m[warp] = nm;
            }
        }
        __syncthreads();

        // --- alpha + aggregation ---
        float al = __expf(sc[t] - run_m[h]);   // thread t covers (h, i)=(t>>6, t&63)
        alphaSm[t] = al;
        float scl = scaleS[h];
        __syncthreads();

        acc *= scl;
#pragma unroll 4
        for (int i = 0; i < cd; i++) {
            int s = srcSm[i];
            acc = fmaf(alphaSm[(h << 6) | i], d_ft[(size_t)s * HF + t], acc);
        }
        __syncthreads();
    }

    out[(size_t)node * HF + t] = acc / run_d[h] + bias[t];
}

extern "C" void kernel_launch(void* const* d_in, const int* in_sizes, int n_in,
                              void* d_out, int out_size) {
    const float* feat = (const float*)d_in[0];
    const int*   src  = (const int*)d_in[1];
    const int*   dst  = (const int*)d_in[2];
    const float* fcw  = (const float*)d_in[3];
    const float* al   = (const float*)d_in[4];
    const float* ar   = (const float*)d_in[5];
    const float* al1  = (const float*)d_in[6];
    const float* ar1  = (const float*)d_in[7];
    const float* bias = (const float*)d_in[8];
    float* out = (float*)d_out;

    int n = in_sizes[0] / FIN;
    int e = in_sizes[1];
    int nb = (n + 255) / 256;

    kinit<<<nb, 256>>>(al, ar, al1, ar1, n);
    khist<<<(e + 255) / 256, 256>>>(dst, e);
    kscanA<<<nb, 256>>>(n);
    kscanB<<<1, 256>>>(nb, n, e);
    kscanC<<<nb, 256>>>(n);
    kscatter<<<(e + 255) / 256, 256>>>(src, dst, e);
    k2_node<<<(n + 7) / 8, 256>>>(feat, n);
    k1_gemm<<<(n + 63) / 64, 256>>>(feat, fcw, n);
    k34_node<<<n, 256>>>(feat, out, bias);
}

// round 5
// speedup vs baseline: 1.4016x; 1.4016x over previous
#include <cuda_runtime.h>
#include <cuda_fp16.h>
#include <math_constants.h>

#define NMAX 50000
#define EMAX 800000
#define FIN 128
#define NHEAD 4
#define HF 256   // NHEAD * F_OUT

// ---- scratch (device globals; no allocation allowed) ----
__device__ __half d_fth[NMAX * HF];        // projected features [N,256], fp16
__device__ float d_e[NHEAD * EMAX];        // edge scores, PLANAR [h][E], CSR order
__device__ int   d_ssrc[EMAX];             // src id, CSR order
__device__ int   d_deg[NMAX];              // degree histogram
__device__ int   d_off[NMAX + 1];          // CSR offsets
__device__ int   d_cur[NMAX];              // scatter cursors
__device__ int   d_bsum[256];              // scan block sums
__device__ int   d_bpre[256];              // scan block prefixes
__device__ float d_el2[NMAX * NHEAD];
__device__ float d_er2[NMAX * NHEAD];
__device__ float d_w[NHEAD * FIN];         // al*ar - 2*al1*ar1
__device__ float d_wl1[NHEAD * FIN];       // al1^2
__device__ float d_wr1[NHEAD * FIN];       // ar1^2

__device__ __forceinline__ float sel4(const float a[4], int l) {
    return l == 0 ? a[0] : l == 1 ? a[1] : l == 2 ? a[2] : a[3];
}
__device__ __forceinline__ int sel4i(const int a[4], int l) {
    return l == 0 ? a[0] : l == 1 ? a[1] : l == 2 ? a[2] : a[3];
}

// packed f32x2 helpers (FFMA2 — only reachable via PTX)
__device__ __forceinline__ unsigned long long pk2(float lo, float hi) {
    unsigned long long r;
    asm("mov.b64 %0, {%1,%2};" : "=l"(r) : "f"(lo), "f"(hi));
    return r;
}
__device__ __forceinline__ void upk2(unsigned long long v, float& lo, float& hi) {
    asm("mov.b64 {%0,%1}, %2;" : "=f"(lo), "=f"(hi) : "l"(v));
}
__device__ __forceinline__ void ffma2(unsigned long long& d, unsigned long long a,
                                      unsigned long long b) {
    asm("fma.rn.f32x2 %0, %1, %2, %0;" : "+l"(d) : "l"(a), "l"(b));
}

// ---- K0: zero degree histogram + combine attention vectors ----
__global__ void kinit(const float* __restrict__ al, const float* __restrict__ ar,
                      const float* __restrict__ al1, const float* __restrict__ ar1, int n) {
    int i = blockIdx.x * 256 + threadIdx.x;
    if (i < n) d_deg[i] = 0;
    if (i < NHEAD * FIN) {
        d_w[i]   = al[i] * ar[i] - 2.0f * al1[i] * ar1[i];
        d_wl1[i] = al1[i] * al1[i];
        d_wr1[i] = ar1[i] * ar1[i];
    }
}

// ---- histogram of dst ----
__global__ void khist(const int* __restrict__ dst, int e) {
    int i = blockIdx.x * blockDim.x + threadIdx.x;
    if (i < e) atomicAdd(&d_deg[dst[i]], 1);
}

// ---- scan A: per-block sums of 256 degrees ----
__global__ void kscanA(int n) {
    __shared__ int sh[256];
    int t = threadIdx.x;
    int i = blockIdx.x * 256 + t;
    sh[t] = (i < n) ? d_deg[i] : 0;
    __syncthreads();
#pragma unroll
    for (int off = 128; off; off >>= 1) {
        if (t < off) sh[t] += sh[t + off];
        __syncthreads();
    }
    if (t == 0) d_bsum[blockIdx.x] = sh[0];
}

// ---- scan B: exclusive scan of block sums (nb <= 256) ----
__global__ void kscanB(int nb, int n, int e) {
    __shared__ int sh[256];
    int t = threadIdx.x;
    sh[t] = (t < nb) ? d_bsum[t] : 0;
    __syncthreads();
#pragma unroll
    for (int off = 1; off < 256; off <<= 1) {
        int x = (t >= off) ? sh[t - off] : 0;
        __syncthreads();
        sh[t] += x;
        __syncthreads();
    }
    if (t < nb) d_bpre[t] = (t ? sh[t - 1] : 0);
    if (t == 0) d_off[n] = e;
}

// ---- scan C: per-block exclusive scan + prefix -> offsets ----
__global__ void kscanC(int n) {
    __shared__ int sh[256];
    int t = threadIdx.x;
    int i = blockIdx.x * 256 + t;
    int v = (i < n) ? d_deg[i] : 0;
    sh[t] = v;
    __syncthreads();
#pragma unroll
    for (int off = 1; off < 256; off <<= 1) {
        int x = (t >= off) ? sh[t - off] : 0;
        __syncthreads();
        sh[t] += x;
        __syncthreads();
    }
    if (i < n) {
        int o = d_bpre[blockIdx.x] + sh[t] - v;  // exclusive
        d_off[i] = o;
        d_cur[i] = o;
    }
}

// ---- K2: per-node el2/er2. One warp per node. ----
__global__ void k2_node(const float* __restrict__ feat, int n) {
    __shared__ float wl[NHEAD * FIN], wr[NHEAD * FIN];
    int t = threadIdx.x;
    wl[t] = d_wl1[t]; wl[t + 256] = d_wl1[t + 256];
    wr[t] = d_wr1[t]; wr[t + 256] = d_wr1[t + 256];
    __syncthreads();
    int warp = t >> 5, lane = t & 31;
    int node = blockIdx.x * 8 + warp;
    if (node >= n) return;

    float4 f = *(const float4*)(feat + (size_t)node * FIN + lane * 4);
    float4 f2 = make_float4(f.x * f.x, f.y * f.y, f.z * f.z, f.w * f.w);
    float accl[4], accr[4];
#pragma unroll
    for (int h = 0; h < 4; h++) {
        const float* a = wl + h * FIN + lane * 4;
        const float* b = wr + h * FIN + lane * 4;
        accl[h] = f2.x * a[0] + f2.y * a[1] + f2.z * a[2] + f2.w * a[3];
        accr[h] = f2.x * b[0] + f2.y * b[1] + f2.z * b[2] + f2.w * b[3];
    }
#pragma unroll
    for (int off = 16; off; off >>= 1) {
#pragma unroll
        for (int h = 0; h < 4; h++) {
            accl[h] += __shfl_xor_sync(0xffffffffu, accl[h], off);
            accr[h] += __shfl_xor_sync(0xffffffffu, accr[h], off);
        }
    }
    if (lane < 4) {
        int idx = node * 4 + lane;
        d_el2[idx] = sel4(accl, lane);
        d_er2[idx] = sel4(accr, lane);
    }
}

// ---- K1: ft = feat @ fc_w^T. 64x256 tile, 8x8 thread tile, FFMA2, half out. ----
__global__ void __launch_bounds__(256) k1_gemm(const float* __restrict__ feat,
                                               const float* __restrict__ fcw, int n) {
    __shared__ float As[64 * 16];    // 4 KB
    __shared__ float Bs[16 * 256];   // 16 KB
    int t = threadIdx.x;
    int tx = t & 31, ty = t >> 5;
    int m0 = blockIdx.x * 64;

    unsigned long long acc2[8][4];
#pragma unroll
    for (int i = 0; i < 8; i++)
#pragma unroll
        for (int j = 0; j < 4; j++) acc2[i][j] = 0ull;

    int arow = t >> 2, akq = (t & 3) * 4;

#pragma unroll
    for (int kc = 0; kc < FIN; kc += 16) {
        float4 av = make_float4(0.f, 0.f, 0.f, 0.f);
        if (m0 + arow < n)
            av = *(const float4*)(feat + (size_t)(m0 + arow) * FIN + kc + akq);
        *(float4*)(As + arow * 16 + akq) = av;
#pragma unroll
        for (int q = 0; q < 4; q++) {
            float4 w4 = *(const float4*)(fcw + (size_t)t * FIN + kc + q * 4);
            Bs[(q * 4 + 0) * 256 + t] = w4.x;
            Bs[(q * 4 + 1) * 256 + t] = w4.y;
            Bs[(q * 4 + 2) * 256 + t] = w4.z;
            Bs[(q * 4 + 3) * 256 + t] = w4.w;
        }
        __syncthreads();

#pragma unroll
        for (int k = 0; k < 16; k++) {
            float4 b0 = *(float4*)&Bs[k * 256 + tx * 8];
            float4 b1 = *(float4*)&Bs[k * 256 + tx * 8 + 4];
            unsigned long long bb0 = pk2(b0.x, b0.y), bb1 = pk2(b0.z, b0.w);
            unsigned long long bb2 = pk2(b1.x, b1.y), bb3 = pk2(b1.z, b1.w);
#pragma unroll
            for (int i = 0; i < 8; i++) {
                float a = As[(ty * 8 + i) * 16 + k];
                unsigned long long aa = pk2(a, a);
                ffma2(acc2[i][0], aa, bb0);
                ffma2(acc2[i][1], aa, bb1);
                ffma2(acc2[i][2], aa, bb2);
                ffma2(acc2[i][3], aa, bb3);
            }
        }
        __syncthreads();
    }

#pragma unroll
    for (int i = 0; i < 8; i++) {
        int row = m0 + ty * 8 + i;
        if (row < n) {
            float v[8];
            upk2(acc2[i][0], v[0], v[1]); upk2(acc2[i][1], v[2], v[3]);
            upk2(acc2[i][2], v[4], v[5]); upk2(acc2[i][3], v[6], v[7]);
            __half2 hv[4];
#pragma unroll
            for (int q = 0; q < 4; q++)
                hv[q] = __floats2half2_rn(v[2 * q], v[2 * q + 1]);
            *(uint4*)(d_fth + (size_t)row * HF + tx * 8) = *(uint4*)hv;
        }
    }
}

// ---- K3: edge scores + scatter into CSR. 4 edges per warp for ILP. ----
__global__ void __launch_bounds__(256) k3_edge(const float* __restrict__ feat,
                                               const int* __restrict__ src,
                                               const int* __restrict__ dst, int eN) {
    __shared__ float ws[NHEAD * FIN];
    int t = threadIdx.x;
    ws[t] = d_w[t]; ws[t + 256] = d_w[t + 256];
    __syncthreads();
    int warp = t >> 5, lane = t & 31;
    int e0 = (blockIdx.x * 8 + warp) * 4;

    int s[4], d[4];
    bool valid[4];
#pragma unroll
    for (int q = 0; q < 4; q++) {
        int e = e0 + q;
        valid[q] = e < eN;
        s[q] = valid[q] ? src[e] : 0;
        d[q] = valid[q] ? dst[e] : 0;
    }

    float acc[4][4];
#pragma unroll
    for (int q = 0; q < 4; q++) {
        float4 fs = *(const float4*)(feat + (size_t)s[q] * FIN + lane * 4);
        float4 fd = *(const float4*)(feat + (size_t)d[q] * FIN + lane * 4);
        float4 p = make_float4(fs.x * fd.x, fs.y * fd.y, fs.z * fd.z, fs.w * fd.w);
#pragma unroll
        for (int h = 0; h < 4; h++) {
            const float* w4 = ws + h * FIN + lane * 4;
            acc[q][h] = p.x * w4[0] + p.y * w4[1] + p.z * w4[2] + p.w * w4[3];
        }
    }
#pragma unroll
    for (int off = 16; off; off >>= 1)
#pragma unroll
        for (int q = 0; q < 4; q++)
#pragma unroll
            for (int h = 0; h < 4; h++)
                acc[q][h] += __shfl_xor_sync(0xffffffffu, acc[q][h], off);

    int pos = 0;
    if (lane < 4 && valid[lane])
        pos = atomicAdd(&d_cur[sel4i(d, lane)], 1);
    if (lane < 4 && valid[lane])
        d_ssrc[pos] = sel4i(s, lane);

#pragma unroll
    for (int q = 0; q < 4; q++) {
        if (!valid[q]) break;
        int pq = __shfl_sync(0xffffffffu, pos, q);
        if (lane < 4) {
            float v = sel4(acc[q], lane);
            v += d_el2[s[q] * 4 + lane] + d_er2[d[q] * 4 + lane];
            d_e[(size_t)lane * EMAX + pq] = v;   // planar [h][E]
        }
    }
}

// ---- K4: per-dst softmax + aggregation (fp16 ft), smem-staged. 1 block/node. ----
__global__ void __launch_bounds__(256) k4_node(float* __restrict__ out,
                                               const float* __restrict__ bias) {
    __shared__ int   srcSm[64];
    __shared__ float alphaSm[256];   // [h][64]
    __shared__ float sh_m[4], sh_inv[4];
    int node = blockIdx.x;
    int t = threadIdx.x;
    int st = d_off[node];
    int deg = d_off[node + 1] - st;

    if (deg == 0) {
        out[(size_t)node * HF + t] = bias[t];
        return;
    }

    int warp = t >> 5, lane = t & 31;
    if (warp < 4) {  // softmax stats: warp = head, planar coalesced reads
        const float* ep = d_e + (size_t)warp * EMAX + st;
        float mx = -CUDART_INF_F;
        for (int i = lane; i < deg; i += 32) mx = fmaxf(mx, ep[i]);
#pragma unroll
        for (int off = 16; off; off >>= 1)
            mx = fmaxf(mx, __shfl_xor_sync(0xffffffffu, mx, off));
        float sm = 0.f;
        for (int i = lane; i < deg; i += 32) sm += __expf(ep[i] - mx);
#pragma unroll
        for (int off = 16; off; off >>= 1)
            sm += __shfl_xor_sync(0xffffffffu, sm, off);
        if (lane == 0) { sh_m[warp] = mx; sh_inv[warp] = 1.0f / sm; }
    }
    __syncthreads();

    int h = t >> 6;
    int i64 = t & 63;
    float mh = sh_m[h], inv = sh_inv[h];
    float acc = 0.f;

    for (int c0 = 0; c0 < deg; c0 += 64) {
        int cd = min(64, deg - c0);
        if (t < cd) srcSm[t] = d_ssrc[st + c0 + t];
        if (i64 < cd)
            alphaSm[t] = __expf(d_e[(size_t)h * EMAX + st + c0 + i64] - mh) * inv;
        __syncthreads();
#pragma unroll 8
        for (int i = 0; i < cd; i++) {
            int s = srcSm[i];
            float fv = __half2float(d_fth[(size_t)s * HF + t]);
            acc = fmaf(alphaSm[(h << 6) | i], fv, acc);
        }
        __syncthreads();
    }
    out[(size_t)node * HF + t] = acc + bias[t];
}

extern "C" void kernel_launch(void* const* d_in, const int* in_sizes, int n_in,
                              void* d_out, int out_size) {
    const float* feat = (const float*)d_in[0];
    const int*   src  = (const int*)d_in[1];
    const int*   dst  = (const int*)d_in[2];
    const float* fcw  = (const float*)d_in[3];
    const float* al   = (const float*)d_in[4];
    const float* ar   = (const float*)d_in[5];
    const float* al1  = (const float*)d_in[6];
    const float* ar1  = (const float*)d_in[7];
    const float* bias = (const float*)d_in[8];
    float* out = (float*)d_out;

    int n = in_sizes[0] / FIN;
    int e = in_sizes[1];
    int nb = (n + 255) / 256;

    kinit<<<nb, 256>>>(al, ar, al1, ar1, n);
    khist<<<(e + 255) / 256, 256>>>(dst, e);
    kscanA<<<nb, 256>>>(n);
    kscanB<<<1, 256>>>(nb, n, e);
    kscanC<<<nb, 256>>>(n);
    k2_node<<<(n + 7) / 8, 256>>>(feat, n);
    k1_gemm<<<(n + 63) / 64, 256>>>(feat, fcw, n);
    k3_edge<<<(e + 31) / 32, 256>>>(feat, src, dst, e);
    k4_node<<<n, 256>>>(out, bias);
}

// round 6
// speedup vs baseline: 1.4926x; 1.0649x over previous
#include <cuda_runtime.h>
#include <cuda_fp16.h>
#include <math_constants.h>

#define NMAX 50000
#define EMAX 800000
#define FIN 128
#define NHEAD 4
#define HF 256   // NHEAD * F_OUT

// ---- scratch (device globals; no allocation allowed) ----
__device__ __half d_fth[NMAX * HF];        // projected features [N,256], fp16
__device__ float d_e[NHEAD * EMAX];        // exp(edge score), PLANAR [h][E], CSR order
__device__ int   d_ssrc[EMAX];             // src id, CSR order
__device__ int   d_deg[NMAX];              // degree histogram
__device__ int   d_off[NMAX + 1];          // CSR offsets
__device__ int   d_cur[NMAX];              // scatter cursors
__device__ int   d_bsum[256];              // scan block sums
__device__ int   d_bpre[256];              // scan block prefixes
__device__ float d_el2[NMAX * NHEAD];
__device__ float d_er2[NMAX * NHEAD];
__device__ float d_inv[NMAX * NHEAD];      // 1 / softmax denom
__device__ float d_w[NHEAD * FIN];         // al*ar - 2*al1*ar1
__device__ float d_wl1[NHEAD * FIN];       // al1^2
__device__ float d_wr1[NHEAD * FIN];       // ar1^2

__device__ __forceinline__ float sel4(const float a[4], int l) {
    return l == 0 ? a[0] : l == 1 ? a[1] : l == 2 ? a[2] : a[3];
}
__device__ __forceinline__ int sel4i(const int a[4], int l) {
    return l == 0 ? a[0] : l == 1 ? a[1] : l == 2 ? a[2] : a[3];
}

// packed f32x2 helpers (FFMA2 — only reachable via PTX)
__device__ __forceinline__ unsigned long long pk2(float lo, float hi) {
    unsigned long long r;
    asm("mov.b64 %0, {%1,%2};" : "=l"(r) : "f"(lo), "f"(hi));
    return r;
}
__device__ __forceinline__ void upk2(unsigned long long v, float& lo, float& hi) {
    asm("mov.b64 {%0,%1}, %2;" : "=f"(lo), "=f"(hi) : "l"(v));
}
__device__ __forceinline__ void ffma2(unsigned long long& d, unsigned long long a,
                                      unsigned long long b) {
    asm("fma.rn.f32x2 %0, %1, %2, %0;" : "+l"(d) : "l"(a), "l"(b));
}

// ---- K0: zero degree histogram + combine attention vectors ----
__global__ void kinit(const float* __restrict__ al, const float* __restrict__ ar,
                      const float* __restrict__ al1, const float* __restrict__ ar1, int n) {
    int i = blockIdx.x * 256 + threadIdx.x;
    if (i < n) d_deg[i] = 0;
    if (i < NHEAD * FIN) {
        d_w[i]   = al[i] * ar[i] - 2.0f * al1[i] * ar1[i];
        d_wl1[i] = al1[i] * al1[i];
        d_wr1[i] = ar1[i] * ar1[i];
    }
}

// ---- histogram of dst ----
__global__ void khist(const int* __restrict__ dst, int e) {
    int i = blockIdx.x * blockDim.x + threadIdx.x;
    if (i < e) atomicAdd(&d_deg[dst[i]], 1);
}

// ---- scan A: per-block sums of 256 degrees ----
__global__ void kscanA(int n) {
    __shared__ int sh[256];
    int t = threadIdx.x;
    int i = blockIdx.x * 256 + t;
    sh[t] = (i < n) ? d_deg[i] : 0;
    __syncthreads();
#pragma unroll
    for (int off = 128; off; off >>= 1) {
        if (t < off) sh[t] += sh[t + off];
        __syncthreads();
    }
    if (t == 0) d_bsum[blockIdx.x] = sh[0];
}

// ---- scan B: exclusive scan of block sums (nb <= 256) ----
__global__ void kscanB(int nb, int n, int e) {
    __shared__ int sh[256];
    int t = threadIdx.x;
    sh[t] = (t < nb) ? d_bsum[t] : 0;
    __syncthreads();
#pragma unroll
    for (int off = 1; off < 256; off <<= 1) {
        int x = (t >= off) ? sh[t - off] : 0;
        __syncthreads();
        sh[t] += x;
        __syncthreads();
    }
    if (t < nb) d_bpre[t] = (t ? sh[t - 1] : 0);
    if (t == 0) d_off[n] = e;
}

// ---- scan C: per-block exclusive scan + prefix -> offsets ----
__global__ void kscanC(int n) {
    __shared__ int sh[256];
    int t = threadIdx.x;
    int i = blockIdx.x * 256 + t;
    int v = (i < n) ? d_deg[i] : 0;
    sh[t] = v;
    __syncthreads();
#pragma unroll
    for (int off = 1; off < 256; off <<= 1) {
        int x = (t >= off) ? sh[t - off] : 0;
        __syncthreads();
        sh[t] += x;
        __syncthreads();
    }
    if (i < n) {
        int o = d_bpre[blockIdx.x] + sh[t] - v;  // exclusive
        d_off[i] = o;
        d_cur[i] = o;
    }
}

// ---- K2: per-node el2/er2. One warp per node. ----
__global__ void k2_node(const float* __restrict__ feat, int n) {
    __shared__ float wl[NHEAD * FIN], wr[NHEAD * FIN];
    int t = threadIdx.x;
    wl[t] = d_wl1[t]; wl[t + 256] = d_wl1[t + 256];
    wr[t] = d_wr1[t]; wr[t + 256] = d_wr1[t + 256];
    __syncthreads();
    int warp = t >> 5, lane = t & 31;
    int node = blockIdx.x * 8 + warp;
    if (node >= n) return;

    float4 f = *(const float4*)(feat + (size_t)node * FIN + lane * 4);
    float4 f2 = make_float4(f.x * f.x, f.y * f.y, f.z * f.z, f.w * f.w);
    float accl[4], accr[4];
#pragma unroll
    for (int h = 0; h < 4; h++) {
        const float* a = wl + h * FIN + lane * 4;
        const float* b = wr + h * FIN + lane * 4;
        accl[h] = f2.x * a[0] + f2.y * a[1] + f2.z * a[2] + f2.w * a[3];
        accr[h] = f2.x * b[0] + f2.y * b[1] + f2.z * b[2] + f2.w * b[3];
    }
#pragma unroll
    for (int off = 16; off; off >>= 1) {
#pragma unroll
        for (int h = 0; h < 4; h++) {
            accl[h] += __shfl_xor_sync(0xffffffffu, accl[h], off);
            accr[h] += __shfl_xor_sync(0xffffffffu, accr[h], off);
        }
    }
    if (lane < 4) {
        int idx = node * 4 + lane;
        d_el2[idx] = sel4(accl, lane);
        d_er2[idx] = sel4(accr, lane);
    }
}

// ---- K1: ft = feat @ fc_w^T. 64x256 tile, 8x8 thread tile, FFMA2, half out. ----
__global__ void __launch_bounds__(256) k1_gemm(const float* __restrict__ feat,
                                               const float* __restrict__ fcw, int n) {
    __shared__ float As[64 * 16];    // 4 KB
    __shared__ float Bs[16 * 256];   // 16 KB
    int t = threadIdx.x;
    int tx = t & 31, ty = t >> 5;
    int m0 = blockIdx.x * 64;

    unsigned long long acc2[8][4];
#pragma unroll
    for (int i = 0; i < 8; i++)
#pragma unroll
        for (int j = 0; j < 4; j++) acc2[i][j] = 0ull;

    int arow = t >> 2, akq = (t & 3) * 4;

#pragma unroll
    for (int kc = 0; kc < FIN; kc += 16) {
        float4 av = make_float4(0.f, 0.f, 0.f, 0.f);
        if (m0 + arow < n)
            av = *(const float4*)(feat + (size_t)(m0 + arow) * FIN + kc + akq);
        *(float4*)(As + arow * 16 + akq) = av;
#pragma unroll
        for (int q = 0; q < 4; q++) {
            float4 w4 = *(const float4*)(fcw + (size_t)t * FIN + kc + q * 4);
            Bs[(q * 4 + 0) * 256 + t] = w4.x;
            Bs[(q * 4 + 1) * 256 + t] = w4.y;
            Bs[(q * 4 + 2) * 256 + t] = w4.z;
            Bs[(q * 4 + 3) * 256 + t] = w4.w;
        }
        __syncthreads();

#pragma unroll
        for (int k = 0; k < 16; k++) {
            float4 b0 = *(float4*)&Bs[k * 256 + tx * 8];
            float4 b1 = *(float4*)&Bs[k * 256 + tx * 8 + 4];
            unsigned long long bb0 = pk2(b0.x, b0.y), bb1 = pk2(b0.z, b0.w);
            unsigned long long bb2 = pk2(b1.x, b1.y), bb3 = pk2(b1.z, b1.w);
#pragma unroll
            for (int i = 0; i < 8; i++) {
                float a = As[(ty * 8 + i) * 16 + k];
                unsigned long long aa = pk2(a, a);
                ffma2(acc2[i][0], aa, bb0);
                ffma2(acc2[i][1], aa, bb1);
                ffma2(acc2[i][2], aa, bb2);
                ffma2(acc2[i][3], aa, bb3);
            }
        }
        __syncthreads();
    }

#pragma unroll
    for (int i = 0; i < 8; i++) {
        int row = m0 + ty * 8 + i;
        if (row < n) {
            float v[8];
            upk2(acc2[i][0], v[0], v[1]); upk2(acc2[i][1], v[2], v[3]);
            upk2(acc2[i][2], v[4], v[5]); upk2(acc2[i][3], v[6], v[7]);
            __half2 hv[4];
#pragma unroll
            for (int q = 0; q < 4; q++)
                hv[q] = __floats2half2_rn(v[2 * q], v[2 * q + 1]);
            *(uint4*)(d_fth + (size_t)row * HF + tx * 8) = *(uint4*)hv;
        }
    }
}

// ---- K3: edge scores -> exp(score) scattered into CSR. 4 edges/warp. ----
__global__ void __launch_bounds__(256) k3_edge(const float* __restrict__ feat,
                                               const int* __restrict__ src,
                                               const int* __restrict__ dst, int eN) {
    __shared__ float ws[NHEAD * FIN];
    int t = threadIdx.x;
    ws[t] = d_w[t]; ws[t + 256] = d_w[t + 256];
    __syncthreads();
    int warp = t >> 5, lane = t & 31;
    int e0 = (blockIdx.x * 8 + warp) * 4;

    int s[4], d[4];
    bool valid[4];
#pragma unroll
    for (int q = 0; q < 4; q++) {
        int e = e0 + q;
        valid[q] = e < eN;
        s[q] = valid[q] ? src[e] : 0;
        d[q] = valid[q] ? dst[e] : 0;
    }

    float acc[4][4];
#pragma unroll
    for (int q = 0; q < 4; q++) {
        float4 fs = *(const float4*)(feat + (size_t)s[q] * FIN + lane * 4);
        float4 fd = *(const float4*)(feat + (size_t)d[q] * FIN + lane * 4);
        float4 p = make_float4(fs.x * fd.x, fs.y * fd.y, fs.z * fd.z, fs.w * fd.w);
#pragma unroll
        for (int h = 0; h < 4; h++) {
            const float* w4 = ws + h * FIN + lane * 4;
            acc[q][h] = p.x * w4[0] + p.y * w4[1] + p.z * w4[2] + p.w * w4[3];
        }
    }
#pragma unroll
    for (int off = 16; off; off >>= 1)
#pragma unroll
        for (int q = 0; q < 4; q++)
#pragma unroll
            for (int h = 0; h < 4; h++)
                acc[q][h] += __shfl_xor_sync(0xffffffffu, acc[q][h], off);

    int pos = 0;
    if (lane < 4 && valid[lane])
        pos = atomicAdd(&d_cur[sel4i(d, lane)], 1);
    if (lane < 4 && valid[lane])
        d_ssrc[pos] = sel4i(s, lane);

#pragma unroll
    for (int q = 0; q < 4; q++) {
        if (!valid[q]) break;
        int pq = __shfl_sync(0xffffffffu, pos, q);
        if (lane < 4) {
            float v = sel4(acc[q], lane);
            v += d_el2[s[q] * 4 + lane] + d_er2[d[q] * 4 + lane];
            d_e[(size_t)lane * EMAX + pq] = __expf(v);   // planar [h][E], max-free
        }
    }
}

// ---- Kdenom: 1/sum(exp) per (node, head). One warp per node, 8 lanes/head. ----
__global__ void kdenom(int n) {
    int gw = (blockIdx.x * 256 + threadIdx.x) >> 5;
    int lane = threadIdx.x & 31;
    if (gw >= n) return;
    int st = d_off[gw], deg = d_off[gw + 1] - st;
    int h = lane >> 3, li = lane & 7;
    float sm = 0.f;
    const float* ep = d_e + (size_t)h * EMAX + st;
    for (int i = li; i < deg; i += 8) sm += ep[i];
#pragma unroll
    for (int off = 4; off; off >>= 1)
        sm += __shfl_xor_sync(0xffffffffu, sm, off);
    if (li == 0) d_inv[gw * 4 + h] = 1.0f / sm;   // inf if deg==0 (never used)
}

// ---- K4: aggregation only (fp16 ft), smem-staged. One block per node. ----
__global__ void __launch_bounds__(256) k4_node(float* __restrict__ out,
                                               const float* __restrict__ bias) {
    __shared__ int   srcSm[64];
    __shared__ float alphaSm[256];   // [h][64]
    int node = blockIdx.x;
    int t = threadIdx.x;
    int st = d_off[node];
    int deg = d_off[node + 1] - st;

    if (deg == 0) {
        out[(size_t)node * HF + t] = bias[t];
        return;
    }

    int h = t >> 6;
    int i64 = t & 63;
    float inv = d_inv[node * 4 + h];
    float acc = 0.f;

    for (int c0 = 0; c0 < deg; c0 += 64) {
        int cd = min(64, deg - c0);
        if (t < cd) srcSm[t] = d_ssrc[st + c0 + t];
        if (i64 < cd)
            alphaSm[t] = d_e[(size_t)h * EMAX + st + c0 + i64] * inv;
        __syncthreads();
#pragma unroll 8
        for (int i = 0; i < cd; i++) {
            int s = srcSm[i];
            float fv = __half2float(d_fth[(size_t)s * HF + t]);
            acc = fmaf(alphaSm[(h << 6) | i], fv, acc);
        }
        __syncthreads();
    }
    out[(size_t)node * HF + t] = acc + bias[t];
}

extern "C" void kernel_launch(void* const* d_in, const int* in_sizes, int n_in,
                              void* d_out, int out_size) {
    const float* feat = (const float*)d_in[0];
    const int*   src  = (const int*)d_in[1];
    const int*   dst  = (const int*)d_in[2];
    const float* fcw  = (const float*)d_in[3];
    const float* al   = (const float*)d_in[4];
    const float* ar   = (const float*)d_in[5];
    const float* al1  = (const float*)d_in[6];
    const float* ar1  = (const float*)d_in[7];
    const float* bias = (const float*)d_in[8];
    float* out = (float*)d_out;

    int n = in_sizes[0] / FIN;
    int e = in_sizes[1];
    int nb = (n + 255) / 256;

    kinit<<<nb, 256>>>(al, ar, al1, ar1, n);
    khist<<<(e + 255) / 256, 256>>>(dst, e);
    kscanA<<<nb, 256>>>(n);
    kscanB<<<1, 256>>>(nb, n, e);
    kscanC<<<nb, 256>>>(n);
    k2_node<<<(n + 7) / 8, 256>>>(feat, n);
    k1_gemm<<<(n + 63) / 64, 256>>>(feat, fcw, n);
    k3_edge<<<(e + 31) / 32, 256>>>(feat, src, dst, e);
    kdenom<<<(n + 7) / 8, 256>>>(n);
    k4_node<<<n, 256>>>(out, bias);
}

// round 8
// speedup vs baseline: 1.9622x; 1.3147x over previous
#include <cuda_runtime.h>
#include <cuda_fp16.h>
#include <math_constants.h>

#define NMAX 50000
#define EMAX 800000
#define FIN 128
#define NHEAD 4
#define HF 256   // NHEAD * F_OUT

// ---- scratch (device globals; no allocation allowed) ----
__device__ __half d_fth[NMAX * HF];        // projected features [N,256], fp16
__device__ float d_e[NHEAD * EMAX];        // exp(edge score), PLANAR [h][E], CSR order
__device__ int   d_ssrc[EMAX];             // src id, CSR order
__device__ int   d_deg[NMAX];              // degree histogram
__device__ int   d_off[NMAX + 1];          // CSR offsets
__device__ int   d_cur[NMAX];              // scatter cursors
__device__ int   d_bsum[256];              // scan block sums
__device__ int   d_bpre[256];              // scan block prefixes
__device__ float d_el2[NMAX * NHEAD];
__device__ float d_er2[NMAX * NHEAD];
__device__ float d_inv[NMAX * NHEAD];      // 1 / softmax denom
__device__ float d_w[NHEAD * FIN];         // al*ar - 2*al1*ar1
__device__ float d_wl1[NHEAD * FIN];       // al1^2
__device__ float d_wr1[NHEAD * FIN];       // ar1^2

__device__ __forceinline__ float sel4(const float a[4], int l) {
    return l == 0 ? a[0] : l == 1 ? a[1] : l == 2 ? a[2] : a[3];
}
__device__ __forceinline__ int sel4i(const int a[4], int l) {
    return l == 0 ? a[0] : l == 1 ? a[1] : l == 2 ? a[2] : a[3];
}

// packed f32x2 helpers (FFMA2 — only reachable via PTX)
__device__ __forceinline__ unsigned long long pk2(float lo, float hi) {
    unsigned long long r;
    asm("mov.b64 %0, {%1,%2};" : "=l"(r) : "f"(lo), "f"(hi));
    return r;
}
__device__ __forceinline__ void upk2(unsigned long long v, float& lo, float& hi) {
    asm("mov.b64 {%0,%1}, %2;" : "=f"(lo), "=f"(hi) : "l"(v));
}
__device__ __forceinline__ void ffma2(unsigned long long& d, unsigned long long a,
                                      unsigned long long b) {
    asm("fma.rn.f32x2 %0, %1, %2, %0;" : "+l"(d) : "l"(a), "l"(b));
}

// ---- K0: zero degree histogram + combine attention vectors ----
__global__ void kinit(const float* __restrict__ al, const float* __restrict__ ar,
                      const float* __restrict__ al1, const float* __restrict__ ar1, int n) {
    int i = blockIdx.x * 256 + threadIdx.x;
    if (i < n) d_deg[i] = 0;
    if (i < NHEAD * FIN) {
        d_w[i]   = al[i] * ar[i] - 2.0f * al1[i] * ar1[i];
        d_wl1[i] = al1[i] * al1[i];
        d_wr1[i] = ar1[i] * ar1[i];
    }
}

// ---- histogram of dst ----
__global__ void khist(const int* __restrict__ dst, int e) {
    int i = blockIdx.x * blockDim.x + threadIdx.x;
    if (i < e) atomicAdd(&d_deg[dst[i]], 1);
}

// ---- scan A: per-block sums of 256 degrees ----
__global__ void kscanA(int n) {
    __shared__ int sh[256];
    int t = threadIdx.x;
    int i = blockIdx.x * 256 + t;
    sh[t] = (i < n) ? d_deg[i] : 0;
    __syncthreads();
#pragma unroll
    for (int off = 128; off; off >>= 1) {
        if (t < off) sh[t] += sh[t + off];
        __syncthreads();
    }
    if (t == 0) d_bsum[blockIdx.x] = sh[0];
}

// ---- scan B: exclusive scan of block sums (nb <= 256) ----
__global__ void kscanB(int nb, int n, int e) {
    __shared__ int sh[256];
    int t = threadIdx.x;
    sh[t] = (t < nb) ? d_bsum[t] : 0;
    __syncthreads();
#pragma unroll
    for (int off = 1; off < 256; off <<= 1) {
        int x = (t >= off) ? sh[t - off] : 0;
        __syncthreads();
        sh[t] += x;
        __syncthreads();
    }
    if (t < nb) d_bpre[t] = (t ? sh[t - 1] : 0);
    if (t == 0) d_off[n] = e;
}

// ---- scan C: per-block exclusive scan + prefix -> offsets ----
__global__ void kscanC(int n) {
    __shared__ int sh[256];
    int t = threadIdx.x;
    int i = blockIdx.x * 256 + t;
    int v = (i < n) ? d_deg[i] : 0;
    sh[t] = v;
    __syncthreads();
#pragma unroll
    for (int off = 1; off < 256; off <<= 1) {
        int x = (t >= off) ? sh[t - off] : 0;
        __syncthreads();
        sh[t] += x;
        __syncthreads();
    }
    if (i < n) {
        int o = d_bpre[blockIdx.x] + sh[t] - v;  // exclusive
        d_off[i] = o;
        d_cur[i] = o;
    }
}

// ---- K2: per-node el2/er2. One warp per node. ----
__global__ void k2_node(const float* __restrict__ feat, int n) {
    __shared__ float wl[NHEAD * FIN], wr[NHEAD * FIN];
    int t = threadIdx.x;
    wl[t] = d_wl1[t]; wl[t + 256] = d_wl1[t + 256];
    wr[t] = d_wr1[t]; wr[t + 256] = d_wr1[t + 256];
    __syncthreads();
    int warp = t >> 5, lane = t & 31;
    int node = blockIdx.x * 8 + warp;
    if (node >= n) return;

    float4 f = *(const float4*)(feat + (size_t)node * FIN + lane * 4);
    float4 f2 = make_float4(f.x * f.x, f.y * f.y, f.z * f.z, f.w * f.w);
    float accl[4], accr[4];
#pragma unroll
    for (int h = 0; h < 4; h++) {
        const float* a = wl + h * FIN + lane * 4;
        const float* b = wr + h * FIN + lane * 4;
        accl[h] = f2.x * a[0] + f2.y * a[1] + f2.z * a[2] + f2.w * a[3];
        accr[h] = f2.x * b[0] + f2.y * b[1] + f2.z * b[2] + f2.w * b[3];
    }
#pragma unroll
    for (int off = 16; off; off >>= 1) {
#pragma unroll
        for (int h = 0; h < 4; h++) {
            accl[h] += __shfl_xor_sync(0xffffffffu, accl[h], off);
            accr[h] += __shfl_xor_sync(0xffffffffu, accr[h], off);
        }
    }
    if (lane < 4) {
        int idx = node * 4 + lane;
        d_el2[idx] = sel4(accl, lane);
        d_er2[idx] = sel4(accr, lane);
    }
}

// ---- K1: ft = feat @ fc_w^T. 64x256 tile, 8x8 thread tile, FFMA2, half out. ----
__global__ void __launch_bounds__(256) k1_gemm(const float* __restrict__ feat,
                                               const float* __restrict__ fcw, int n) {
    __shared__ float As[64 * 16];    // 4 KB
    __shared__ float Bs[16 * 256];   // 16 KB
    int t = threadIdx.x;
    int tx = t & 31, ty = t >> 5;
    int m0 = blockIdx.x * 64;

    unsigned long long acc2[8][4];
#pragma unroll
    for (int i = 0; i < 8; i++)
#pragma unroll
        for (int j = 0; j < 4; j++) acc2[i][j] = 0ull;

    int arow = t >> 2, akq = (t & 3) * 4;

#pragma unroll
    for (int kc = 0; kc < FIN; kc += 16) {
        float4 av = make_float4(0.f, 0.f, 0.f, 0.f);
        if (m0 + arow < n)
            av = *(const float4*)(feat + (size_t)(m0 + arow) * FIN + kc + akq);
        *(float4*)(As + arow * 16 + akq) = av;
#pragma unroll
        for (int q = 0; q < 4; q++) {
            float4 w4 = *(const float4*)(fcw + (size_t)t * FIN + kc + q * 4);
            Bs[(q * 4 + 0) * 256 + t] = w4.x;
            Bs[(q * 4 + 1) * 256 + t] = w4.y;
            Bs[(q * 4 + 2) * 256 + t] = w4.z;
            Bs[(q * 4 + 3) * 256 + t] = w4.w;
        }
        __syncthreads();

#pragma unroll
        for (int k = 0; k < 16; k++) {
            float4 b0 = *(float4*)&Bs[k * 256 + tx * 8];
            float4 b1 = *(float4*)&Bs[k * 256 + tx * 8 + 4];
            unsigned long long bb0 = pk2(b0.x, b0.y), bb1 = pk2(b0.z, b0.w);
            unsigned long long bb2 = pk2(b1.x, b1.y), bb3 = pk2(b1.z, b1.w);
#pragma unroll
            for (int i = 0; i < 8; i++) {
                float a = As[(ty * 8 + i) * 16 + k];
                unsigned long long aa = pk2(a, a);
                ffma2(acc2[i][0], aa, bb0);
                ffma2(acc2[i][1], aa, bb1);
                ffma2(acc2[i][2], aa, bb2);
                ffma2(acc2[i][3], aa, bb3);
            }
        }
        __syncthreads();
    }

#pragma unroll
    for (int i = 0; i < 8; i++) {
        int row = m0 + ty * 8 + i;
        if (row < n) {
            float v[8];
            upk2(acc2[i][0], v[0], v[1]); upk2(acc2[i][1], v[2], v[3]);
            upk2(acc2[i][2], v[4], v[5]); upk2(acc2[i][3], v[6], v[7]);
            __half2 hv[4];
#pragma unroll
            for (int q = 0; q < 4; q++)
                hv[q] = __floats2half2_rn(v[2 * q], v[2 * q + 1]);
            *(uint4*)(d_fth + (size_t)row * HF + tx * 8) = *(uint4*)hv;
        }
    }
}

// ---- K3: edge scores -> exp(score) into CSR. 4 edges/warp, fold-reduce. ----
__global__ void __launch_bounds__(256) k3_edge(const float* __restrict__ feat,
                                               const int* __restrict__ src,
                                               const int* __restrict__ dst, int eN) {
    __shared__ float ws[NHEAD * FIN];
    int t = threadIdx.x;
    ws[t] = d_w[t]; ws[t + 256] = d_w[t + 256];
    __syncthreads();
    int warp = t >> 5, lane = t & 31;
    int e0 = (blockIdx.x * 8 + warp) * 4;

    int s[4], d[4];
    bool valid[4];
#pragma unroll
    for (int q = 0; q < 4; q++) {
        int e = e0 + q;
        valid[q] = e < eN;
        s[q] = valid[q] ? src[e] : 0;
        d[q] = valid[q] ? dst[e] : 0;
    }

    float v[16];   // [q*4+h] per-lane partials
#pragma unroll
    for (int q = 0; q < 4; q++) {
        float4 fs = *(const float4*)(feat + (size_t)s[q] * FIN + lane * 4);
        float4 fd = *(const float4*)(feat + (size_t)d[q] * FIN + lane * 4);
        float4 p = make_float4(fs.x * fd.x, fs.y * fd.y, fs.z * fd.z, fs.w * fd.w);
#pragma unroll
        for (int h = 0; h < 4; h++) {
            const float* w4 = ws + h * FIN + lane * 4;
            v[q * 4 + h] = p.x * w4[0] + p.y * w4[1] + p.z * w4[2] + p.w * w4[3];
        }
    }

    // fold-reduce: 16 values over 32 lanes in 16 shfls
    {
        bool b = (lane & 16) != 0;
#pragma unroll
        for (int i = 0; i < 8; i++) {
            float snd = b ? v[i] : v[i + 8];
            float o = __shfl_xor_sync(0xffffffffu, snd, 16);
            v[i] = (b ? v[i + 8] : v[i]) + o;
        }
        b = (lane & 8) != 0;
#pragma unroll
        for (int i = 0; i < 4; i++) {
            float snd = b ? v[i] : v[i + 4];
            float o = __shfl_xor_sync(0xffffffffu, snd, 8);
            v[i] = (b ? v[i + 4] : v[i]) + o;
        }
        b = (lane & 4) != 0;
#pragma unroll
        for (int i = 0; i < 2; i++) {
            float snd = b ? v[i] : v[i + 2];
            float o = __shfl_xor_sync(0xffffffffu, snd, 4);
            v[i] = (b ? v[i + 2] : v[i]) + o;
        }
        b = (lane & 2) != 0;
        {
            float snd = b ? v[0] : v[1];
            float o = __shfl_xor_sync(0xffffffffu, snd, 2);
            v[0] = (b ? v[1] : v[0]) + o;
        }
        v[0] += __shfl_xor_sync(0xffffffffu, v[0], 1);
    }
    // lane (even) holds sum for vidx; vidx bits from lane bits 4..1
    int vidx = (((lane >> 4) & 1) << 3) | (((lane >> 3) & 1) << 2)
             | (((lane >> 2) & 1) << 1) | ((lane >> 1) & 1);
    int q = vidx >> 2, h = vidx & 3;

    // CSR slots: lanes 0..3 grab positions for their edge
    int pos = 0;
    if (lane < 4 && valid[lane]) {
        pos = atomicAdd(&d_cur[sel4i(d, lane)], 1);
        d_ssrc[pos] = sel4i(s, lane);
    }
    int pq = __shfl_sync(0xffffffffu, pos, q);

    if (((lane & 1) == 0) && ((e0 + q) < eN)) {
        int sq = sel4i(s, q), dq = sel4i(d, q);
        float sc = v[0] + d_el2[sq * 4 + h] + d_er2[dq * 4 + h];
        d_e[(size_t)h * EMAX + pq] = __expf(sc);   // planar [h][E], max-free
    }
}

// ---- Kdenom: 1/sum(exp) per (node, head). One warp per node, 8 lanes/head. ----
__global__ void kdenom(int n) {
    int gw = (blockIdx.x * 256 + threadIdx.x) >> 5;
    int lane = threadIdx.x & 31;
    if (gw >= n) return;
    int st = d_off[gw], deg = d_off[gw + 1] - st;
    int h = lane >> 3, li = lane & 7;
    float sm = 0.f;
    const float* ep = d_e + (size_t)h * EMAX + st;
    for (int i = li; i < deg; i += 8) sm += ep[i];
#pragma unroll
    for (int off = 4; off; off >>= 1)
        sm += __shfl_xor_sync(0xffffffffu, sm, off);
    if (li == 0) d_inv[gw * 4 + h] = 1.0f / sm;   // inf if deg==0 (never used)
}

// ---- K4: aggregation (fp16 ft, half2/thread). 128 threads, one node/block. ----
__global__ void __launch_bounds__(128) k4_node(float* __restrict__ out,
                                               const float* __restrict__ bias) {
    __shared__ int   srcSm[64];
    __shared__ float alSm[256];   // [h][64] raw exp(e)
    int node = blockIdx.x;
    int t = threadIdx.x;          // covers cols 2t, 2t+1
    int st = d_off[node];
    int deg = d_off[node + 1] - st;

    float2* o2 = (float2*)(out + (size_t)node * HF) + t;
    const float2* b2 = (const float2*)bias + t;
    if (deg == 0) {
        *o2 = *b2;
        return;
    }

    int h = t >> 5;               // head of cols 2t,2t+1
    float inv = d_inv[node * 4 + h];
    float ax = 0.f, ay = 0.f;
    const __half2* fbase = (const __half2*)d_fth;

    for (int c0 = 0; c0 < deg; c0 += 64) {
        int cd = min(64, deg - c0);
        if (t < cd) srcSm[t] = d_ssrc[st + c0 + t];
#pragma unroll
        for (int rr = 0; rr < 2; rr++) {
            int idx = t + rr * 128;           // 0..255
            int hh = idx >> 6, ii = idx & 63;
            if (ii < cd) alSm[idx] = d_e[(size_t)hh * EMAX + st + c0 + ii];
        }
        __syncthreads();
#pragma unroll 8
        for (int i = 0; i < cd; i++) {
            int sId = srcSm[i];
            float2 f = __half22float2(fbase[(size_t)sId * 128 + t]);
            float a = alSm[(h << 6) | i];
            ax = fmaf(a, f.x, ax);
            ay = fmaf(a, f.y, ay);
        }
        __syncthreads();
    }
    float2 bb = *b2;
    float2 r;
    r.x = ax * inv + bb.x;
    r.y = ay * inv + bb.y;
    *o2 = r;
}

extern "C" void kernel_launch(void* const* d_in, const int* in_sizes, int n_in,
                              void* d_out, int out_size) {
    const float* feat = (const float*)d_in[0];
    const int*   src  = (const int*)d_in[1];
    const int*   dst  = (const int*)d_in[2];
    const float* fcw  = (const float*)d_in[3];
    const float* al   = (const float*)d_in[4];
    const float* ar   = (const float*)d_in[5];
    const float* al1  = (const float*)d_in[6];
    const float* ar1  = (const float*)d_in[7];
    const float* bias = (const float*)d_in[8];
    float* out = (float*)d_out;

    int n = in_sizes[0] / FIN;
    int e = in_sizes[1];
    int nb = (n + 255) / 256;

    kinit<<<nb, 256>>>(al, ar, al1, ar1, n);
    khist<<<(e + 255) / 256, 256>>>(dst, e);
    kscanA<<<nb, 256>>>(n);
    kscanB<<<1, 256>>>(nb, n, e);
    kscanC<<<nb, 256>>>(n);
    k2_node<<<(n + 7) / 8, 256>>>(feat, n);
    k1_gemm<<<(n + 63) / 64, 256>>>(feat, fcw, n);
    k3_edge<<<(e + 31) / 32, 256>>>(feat, src, dst, e);
    kdenom<<<(n + 7) / 8, 256>>>(n);
    k4_node<<<n, 128>>>(out, bias);
}

// round 10
// speedup vs baseline: 1.9720x; 1.0050x over previous
#include <cuda_runtime.h>
#include <cuda_fp16.h>
#include <math_constants.h>

#define NMAX 50000
#define EMAX 800000
#define FIN 128
#define NHEAD 4
#define HF 256   // NHEAD * F_OUT

// ---- scratch (device globals; no allocation allowed) ----
__device__ __half d_fth[NMAX * HF];        // projected features [N,256], fp16
__device__ __half d_feath[NMAX * FIN];     // fp16 copy of feat for scoring
__device__ float d_e[NHEAD * EMAX];        // exp(edge score), PLANAR [h][E], CSR order
__device__ int   d_ssrc[EMAX];             // src id, CSR order
__device__ int   d_deg[NMAX];              // degree histogram
__device__ int   d_off[NMAX + 1];          // CSR offsets
__device__ int   d_cur[NMAX];              // scatter cursors
__device__ int   d_bsum[256];              // scan block sums
__device__ int   d_bpre[256];              // scan block prefixes
__device__ float d_el2[NMAX * NHEAD];
__device__ float d_er2[NMAX * NHEAD];
__device__ float d_inv[NMAX * NHEAD];      // 1 / softmax denom
__device__ float d_w[NHEAD * FIN];         // al*ar - 2*al1*ar1
__device__ float d_wl1[NHEAD * FIN];       // al1^2
__device__ float d_wr1[NHEAD * FIN];       // ar1^2

__device__ __forceinline__ float sel4(const float a[4], int l) {
    return l == 0 ? a[0] : l == 1 ? a[1] : l == 2 ? a[2] : a[3];
}
__device__ __forceinline__ int sel4i(const int a[4], int l) {
    return l == 0 ? a[0] : l == 1 ? a[1] : l == 2 ? a[2] : a[3];
}

// packed f32x2 helpers (FFMA2 — only reachable via PTX)
__device__ __forceinline__ unsigned long long pk2(float lo, float hi) {
    unsigned long long r;
    asm("mov.b64 %0, {%1,%2};" : "=l"(r) : "f"(lo), "f"(hi));
    return r;
}
__device__ __forceinline__ void upk2(unsigned long long v, float& lo, float& hi) {
    asm("mov.b64 {%0,%1}, %2;" : "=f"(lo), "=f"(hi) : "l"(v));
}
__device__ __forceinline__ void ffma2(unsigned long long& d, unsigned long long a,
                                      unsigned long long b) {
    asm("fma.rn.f32x2 %0, %1, %2, %0;" : "+l"(d) : "l"(a), "l"(b));
}

// ---- K0: zero degree histogram + combine attention vectors ----
__global__ void kinit(const float* __restrict__ al, const float* __restrict__ ar,
                      const float* __restrict__ al1, const float* __restrict__ ar1, int n) {
    int i = blockIdx.x * 256 + threadIdx.x;
    if (i < n) d_deg[i] = 0;
    if (i < NHEAD * FIN) {
        d_w[i]   = al[i] * ar[i] - 2.0f * al1[i] * ar1[i];
        d_wl1[i] = al1[i] * al1[i];
        d_wr1[i] = ar1[i] * ar1[i];
    }
}

// ---- histogram of dst ----
__global__ void khist(const int* __restrict__ dst, int e) {
    int i = blockIdx.x * blockDim.x + threadIdx.x;
    if (i < e) atomicAdd(&d_deg[dst[i]], 1);
}

// ---- convert feat to fp16 (vectorized float4 -> 4 half) ----
__global__ void kcvt(const float* __restrict__ feat, int total4) {
    int i = blockIdx.x * 256 + threadIdx.x;
    if (i < total4) {
        float4 v = ((const float4*)feat)[i];
        uint2 r;
        *(__half2*)&r.x = __floats2half2_rn(v.x, v.y);
        *(__half2*)&r.y = __floats2half2_rn(v.z, v.w);
        ((uint2*)d_feath)[i] = r;
    }
}

// ---- scan A: per-block sums of 256 degrees ----
__global__ void kscanA(int n) {
    __shared__ int sh[256];
    int t = threadIdx.x;
    int i = blockIdx.x * 256 + t;
    sh[t] = (i < n) ? d_deg[i] : 0;
    __syncthreads();
#pragma unroll
    for (int off = 128; off; off >>= 1) {
        if (t < off) sh[t] += sh[t + off];
        __syncthreads();
    }
    if (t == 0) d_bsum[blockIdx.x] = sh[0];
}

// ---- scan B: exclusive scan of block sums (nb <= 256) ----
__global__ void kscanB(int nb, int n, int e) {
    __shared__ int sh[256];
    int t = threadIdx.x;
    sh[t] = (t < nb) ? d_bsum[t] : 0;
    __syncthreads();
#pragma unroll
    for (int off = 1; off < 256; off <<= 1) {
        int x = (t >= off) ? sh[t - off] : 0;
        __syncthreads();
        sh[t] += x;
        __syncthreads();
    }
    if (t < nb) d_bpre[t] = (t ? sh[t - 1] : 0);
    if (t == 0) d_off[n] = e;
}

// ---- scan C: per-block exclusive scan + prefix -> offsets ----
__global__ void kscanC(int n) {
    __shared__ int sh[256];
    int t = threadIdx.x;
    int i = blockIdx.x * 256 + t;
    int v = (i < n) ? d_deg[i] : 0;
    sh[t] = v;
    __syncthreads();
#pragma unroll
    for (int off = 1; off < 256; off <<= 1) {
        int x = (t >= off) ? sh[t - off] : 0;
        __syncthreads();
        sh[t] += x;
        __syncthreads();
    }
    if (i < n) {
        int o = d_bpre[blockIdx.x] + sh[t] - v;  // exclusive
        d_off[i] = o;
        d_cur[i] = o;
    }
}

// ---- K2: per-node el2/er2. One warp per node. ----
__global__ void k2_node(const float* __restrict__ feat, int n) {
    __shared__ float wl[NHEAD * FIN], wr[NHEAD * FIN];
    int t = threadIdx.x;
    wl[t] = d_wl1[t]; wl[t + 256] = d_wl1[t + 256];
    wr[t] = d_wr1[t]; wr[t + 256] = d_wr1[t + 256];
    __syncthreads();
    int warp = t >> 5, lane = t & 31;
    int node = blockIdx.x * 8 + warp;
    if (node >= n) return;

    float4 f = *(const float4*)(feat + (size_t)node * FIN + lane * 4);
    float4 f2 = make_float4(f.x * f.x, f.y * f.y, f.z * f.z, f.w * f.w);
    float accl[4], accr[4];
#pragma unroll
    for (int h = 0; h < 4; h++) {
        const float* a = wl + h * FIN + lane * 4;
        const float* b = wr + h * FIN + lane * 4;
        accl[h] = f2.x * a[0] + f2.y * a[1] + f2.z * a[2] + f2.w * a[3];
        accr[h] = f2.x * b[0] + f2.y * b[1] + f2.z * b[2] + f2.w * b[3];
    }
#pragma unroll
    for (int off = 16; off; off >>= 1) {
#pragma unroll
        for (int h = 0; h < 4; h++) {
            accl[h] += __shfl_xor_sync(0xffffffffu, accl[h], off);
            accr[h] += __shfl_xor_sync(0xffffffffu, accr[h], off);
        }
    }
    if (lane < 4) {
        int idx = node * 4 + lane;
        d_el2[idx] = sel4(accl, lane);
        d_er2[idx] = sel4(accr, lane);
    }
}

// ---- K1: ft = feat @ fc_w^T. 64x256 tile, 8x8 thread tile, FFMA2, half out. ----
__global__ void __launch_bounds__(256) k1_gemm(const float* __restrict__ feat,
                                               const float* __restrict__ fcw, int n) {
    __shared__ float As[64 * 16];    // 4 KB
    __shared__ float Bs[16 * 256];   // 16 KB
    int t = threadIdx.x;
    int tx = t & 31, ty = t >> 5;
    int m0 = blockIdx.x * 64;

    unsigned long long acc2[8][4];
#pragma unroll
    for (int i = 0; i < 8; i++)
#pragma unroll
        for (int j = 0; j < 4; j++) acc2[i][j] = 0ull;

    int arow = t >> 2, akq = (t & 3) * 4;

#pragma unroll
    for (int kc = 0; kc < FIN; kc += 16) {
        float4 av = make_float4(0.f, 0.f, 0.f, 0.f);
        if (m0 + arow < n)
            av = *(const float4*)(feat + (size_t)(m0 + arow) * FIN + kc + akq);
        *(float4*)(As + arow * 16 + akq) = av;
#pragma unroll
        for (int q = 0; q < 4; q++) {
            float4 w4 = *(const float4*)(fcw + (size_t)t * FIN + kc + q * 4);
            Bs[(q * 4 + 0) * 256 + t] = w4.x;
            Bs[(q * 4 + 1) * 256 + t] = w4.y;
            Bs[(q * 4 + 2) * 256 + t] = w4.z;
            Bs[(q * 4 + 3) * 256 + t] = w4.w;
        }
        __syncthreads();

#pragma unroll
        for (int k = 0; k < 16; k++) {
            float4 b0 = *(float4*)&Bs[k * 256 + tx * 8];
            float4 b1 = *(float4*)&Bs[k * 256 + tx * 8 + 4];
            unsigned long long bb0 = pk2(b0.x, b0.y), bb1 = pk2(b0.z, b0.w);
            unsigned long long bb2 = pk2(b1.x, b1.y), bb3 = pk2(b1.z, b1.w);
#pragma unroll
            for (int i = 0; i < 8; i++) {
                float a = As[(ty * 8 + i) * 16 + k];
                unsigned long long aa = pk2(a, a);
                ffma2(acc2[i][0], aa, bb0);
                ffma2(acc2[i][1], aa, bb1);
                ffma2(acc2[i][2], aa, bb2);
                ffma2(acc2[i][3], aa, bb3);
            }
        }
        __syncthreads();
    }

#pragma unroll
    for (int i = 0; i < 8; i++) {
        int row = m0 + ty * 8 + i;
        if (row < n) {
            float v[8];
            upk2(acc2[i][0], v[0], v[1]); upk2(acc2[i][1], v[2], v[3]);
            upk2(acc2[i][2], v[4], v[5]); upk2(acc2[i][3], v[6], v[7]);
            __half2 hv[4];
#pragma unroll
            for (int q = 0; q < 4; q++)
                hv[q] = __floats2half2_rn(v[2 * q], v[2 * q + 1]);
            *(uint4*)(d_fth + (size_t)row * HF + tx * 8) = *(uint4*)hv;
        }
    }
}

// ---- K3: edge scores (fp16 feat) -> exp into CSR. 4 edges/warp, fold-reduce. ----
__global__ void __launch_bounds__(256) k3_edge(const int* __restrict__ src,
                                               const int* __restrict__ dst, int eN) {
    __shared__ float ws[NHEAD * FIN];
    int t = threadIdx.x;
    ws[t] = d_w[t]; ws[t + 256] = d_w[t + 256];
    __syncthreads();
    int warp = t >> 5, lane = t & 31;
    int e0 = (blockIdx.x * 8 + warp) * 4;

    int s[4], d[4];
    bool valid[4];
#pragma unroll
    for (int q = 0; q < 4; q++) {
        int e = e0 + q;
        valid[q] = e < eN;
        s[q] = valid[q] ? src[e] : 0;
        d[q] = valid[q] ? dst[e] : 0;
    }

    float v[16];   // [q*4+h] per-lane partials
#pragma unroll
    for (int q = 0; q < 4; q++) {
        uint2 ua = *(const uint2*)(d_feath + (size_t)s[q] * FIN + lane * 4);
        uint2 ub = *(const uint2*)(d_feath + (size_t)d[q] * FIN + lane * 4);
        float2 pa = __half22float2(__hmul2(*(__half2*)&ua.x, *(__half2*)&ub.x));
        float2 pb = __half22float2(__hmul2(*(__half2*)&ua.y, *(__half2*)&ub.y));
#pragma unroll
        for (int h = 0; h < 4; h++) {
            const float* w4 = ws + h * FIN + lane * 4;
            v[q * 4 + h] = pa.x * w4[0] + pa.y * w4[1] + pb.x * w4[2] + pb.y * w4[3];
        }
    }

    // fold-reduce: 16 values over 32 lanes in 16 shfls
    {
        bool b = (lane & 16) != 0;
#pragma unroll
        for (int i = 0; i < 8; i++) {
            float snd = b ? v[i] : v[i + 8];
            float o = __shfl_xor_sync(0xffffffffu, snd, 16);
            v[i] = (b ? v[i + 8] : v[i]) + o;
        }
        b = (lane & 8) != 0;
#pragma unroll
        for (int i = 0; i < 4; i++) {
            float snd = b ? v[i] : v[i + 4];
            float o = __shfl_xor_sync(0xffffffffu, snd, 8);
            v[i] = (b ? v[i + 4] : v[i]) + o;
        }
        b = (lane & 4) != 0;
#pragma unroll
        for (int i = 0; i < 2; i++) {
            float snd = b ? v[i] : v[i + 2];
            float o = __shfl_xor_sync(0xffffffffu, snd, 4);
            v[i] = (b ? v[i + 2] : v[i]) + o;
        }
        b = (lane & 2) != 0;
        {
            float snd = b ? v[0] : v[1];
            float o = __shfl_xor_sync(0xffffffffu, snd, 2);
            v[0] = (b ? v[1] : v[0]) + o;
        }
        v[0] += __shfl_xor_sync(0xffffffffu, v[0], 1);
    }
    // even lane holds sum for vidx; vidx bits from lane bits 4..1
    int vidx = (((lane >> 4) & 1) << 3) | (((lane >> 3) & 1) << 2)
             | (((lane >> 2) & 1) << 1) | ((lane >> 1) & 1);
    int q = vidx >> 2, h = vidx & 3;

    // CSR slots: lanes 0..3 grab positions for their edge
    int pos = 0;
    if (lane < 4 && valid[lane]) {
        pos = atomicAdd(&d_cur[sel4i(d, lane)], 1);
        d_ssrc[pos] = sel4i(s, lane);
    }
    int pq = __shfl_sync(0xffffffffu, pos, q);

    if (((lane & 1) == 0) && ((e0 + q) < eN)) {
        int sq = sel4i(s, q), dq = sel4i(d, q);
        float sc = v[0] + d_el2[sq * 4 + h] + d_er2[dq * 4 + h];
        d_e[(size_t)h * EMAX + pq] = __expf(sc);   // planar [h][E], max-free
    }
}

// ---- Kdenom: 1/sum(exp) per (node, head). One warp per node, 8 lanes/head. ----
__global__ void kdenom(int n) {
    int gw = (blockIdx.x * 256 + threadIdx.x) >> 5;
    int lane = threadIdx.x & 31;
    if (gw >= n) return;
    int st = d_off[gw], deg = d_off[gw + 1] - st;
    int h = lane >> 3, li = lane & 7;
    float sm = 0.f;
    const float* ep = d_e + (size_t)h * EMAX + st;
    for (int i = li; i < deg; i += 8) sm += ep[i];
#pragma unroll
    for (int off = 4; off; off >>= 1)
        sm += __shfl_xor_sync(0xffffffffu, sm, off);
    if (li == 0) d_inv[gw * 4 + h] = 1.0f / sm;   // inf if deg==0 (never used)
}

// ---- K4: aggregation (fp16 ft, half2/thread). 128 threads, one node/block. ----
__global__ void __launch_bounds__(128) k4_node(float* __restrict__ out,
                                               const float* __restrict__ bias) {
    __shared__ int   srcSm[64];
    __shared__ float alSm[256];   // [h][64] raw exp(e)
    int node = blockIdx.x;
    int t = threadIdx.x;          // covers cols 2t, 2t+1
    int st = d_off[node];
    int deg = d_off[node + 1] - st;

    float2* o2 = (float2*)(out + (size_t)node * HF) + t;
    const float2* b2 = (const float2*)bias + t;
    if (deg == 0) {
        *o2 = *b2;
        return;
    }

    int h = t >> 5;               // head of cols 2t,2t+1
    float inv = d_inv[node * 4 + h];
    float ax = 0.f, ay = 0.f;
    const __half2* fbase = (const __half2*)d_fth;

    for (int c0 = 0; c0 < deg; c0 += 64) {
        int cd = min(64, deg - c0);
        if (t < cd) srcSm[t] = d_ssrc[st + c0 + t];
#pragma unroll
        for (int rr = 0; rr < 2; rr++) {
            int idx = t + rr * 128;           // 0..255
            int hh = idx >> 6, ii = idx & 63;
            if (ii < cd) alSm[idx] = d_e[(size_t)hh * EMAX + st + c0 + ii];
        }
        __syncthreads();
#pragma unroll 8
        for (int i = 0; i < cd; i++) {
            int sId = srcSm[i];
            float2 f = __half22float2(fbase[(size_t)sId * 128 + t]);
            float a = alSm[(h << 6) | i];
            ax = fmaf(a, f.x, ax);
            ay = fmaf(a, f.y, ay);
        }
        __syncthreads();
    }
    float2 bb = *b2;
    float2 r;
    r.x = ax * inv + bb.x;
    r.y = ay * inv + bb.y;
    *o2 = r;
}

extern "C" void kernel_launch(void* const* d_in, const int* in_sizes, int n_in,
                              void* d_out, int out_size) {
    const float* feat = (const float*)d_in[0];
    const int*   src  = (const int*)d_in[1];
    const int*   dst  = (const int*)d_in[2];
    const float* fcw  = (const float*)d_in[3];
    const float* al   = (const float*)d_in[4];
    const float* ar   = (const float*)d_in[5];
    const float* al1  = (const float*)d_in[6];
    const float* ar1  = (const float*)d_in[7];
    const float* bias = (const float*)d_in[8];
    float* out = (float*)d_out;

    int n = in_sizes[0] / FIN;
    int e = in_sizes[1];
    int nb = (n + 255) / 256;
    int t4 = n * FIN / 4;

    kinit<<<nb, 256>>>(al, ar, al1, ar1, n);          // 1
    khist<<<(e + 255) / 256, 256>>>(dst, e);          // 2
    kcvt<<<(t4 + 255) / 256, 256>>>(feat, t4);        // 3
    k1_gemm<<<(n + 63) / 64, 256>>>(feat, fcw, n);    // 4  <- profiled slot
    kscanA<<<nb, 256>>>(n);                            // 5
    kscanB<<<1, 256>>>(nb, n, e);                      // 6
    kscanC<<<nb, 256>>>(n);                            // 7
    k2_node<<<(n + 7) / 8, 256>>>(feat, n);            // 8
    k3_edge<<<(e + 31) / 32, 256>>>(src, dst, e);      // 9
    kdenom<<<(n + 7) / 8, 256>>>(n);                   // 10
    k4_node<<<n, 128>>>(out, bias);                    // 11
}

// round 11
// speedup vs baseline: 2.1255x; 1.0778x over previous
#include <cuda_runtime.h>
#include <cuda_fp16.h>
#include <math_constants.h>

#define NMAX 50000
#define EMAX 800000
#define FIN 128
#define NHEAD 4
#define HF 256   // NHEAD * F_OUT

// ---- scratch (device globals; no allocation allowed) ----
__device__ __half d_fth[NMAX * HF];        // projected features [N,256], fp16
__device__ __half d_feath[NMAX * FIN];     // fp16 copy of feat for scoring
__device__ float d_fcwT[HF * FIN];         // fc_w transposed: [k][j]
__device__ float d_e[NHEAD * EMAX];        // exp(edge score), PLANAR [h][E], CSR order
__device__ int   d_ssrc[EMAX];             // src id, CSR order
__device__ int   d_deg[NMAX];              // degree histogram
__device__ int   d_off[NMAX + 1];          // CSR offsets
__device__ int   d_cur[NMAX];              // scatter cursors
__device__ int   d_bsum[256];              // scan block sums
__device__ int   d_bpre[256];              // scan block prefixes
__device__ float d_el2[NMAX * NHEAD];
__device__ float d_er2[NMAX * NHEAD];
__device__ float d_inv[NMAX * NHEAD];      // 1 / softmax denom
__device__ float d_w[NHEAD * FIN];         // al*ar - 2*al1*ar1
__device__ float d_wl1[NHEAD * FIN];       // al1^2
__device__ float d_wr1[NHEAD * FIN];       // ar1^2

__device__ __forceinline__ float sel4(const float a[4], int l) {
    return l == 0 ? a[0] : l == 1 ? a[1] : l == 2 ? a[2] : a[3];
}
__device__ __forceinline__ int sel4i(const int a[4], int l) {
    return l == 0 ? a[0] : l == 1 ? a[1] : l == 2 ? a[2] : a[3];
}

// packed f32x2 helpers (FFMA2 — only reachable via PTX)
__device__ __forceinline__ unsigned long long pk2(float lo, float hi) {
    unsigned long long r;
    asm("mov.b64 %0, {%1,%2};" : "=l"(r) : "f"(lo), "f"(hi));
    return r;
}
__device__ __forceinline__ void upk2(unsigned long long v, float& lo, float& hi) {
    asm("mov.b64 {%0,%1}, %2;" : "=f"(lo), "=f"(hi) : "l"(v));
}
__device__ __forceinline__ void ffma2(unsigned long long& d, unsigned long long a,
                                      unsigned long long b) {
    asm("fma.rn.f32x2 %0, %1, %2, %0;" : "+l"(d) : "l"(a), "l"(b));
}

// ---- K0: zero degree histogram + combine attention vectors ----
__global__ void kinit(const float* __restrict__ al, const float* __restrict__ ar,
                      const float* __restrict__ al1, const float* __restrict__ ar1, int n) {
    int i = blockIdx.x * 256 + threadIdx.x;
    if (i < n) d_deg[i] = 0;
    if (i < NHEAD * FIN) {
        d_w[i]   = al[i] * ar[i] - 2.0f * al1[i] * ar1[i];
        d_wl1[i] = al1[i] * al1[i];
        d_wr1[i] = ar1[i] * ar1[i];
    }
}

// ---- histogram of dst ----
__global__ void khist(const int* __restrict__ dst, int e) {
    int i = blockIdx.x * blockDim.x + threadIdx.x;
    if (i < e) atomicAdd(&d_deg[dst[i]], 1);
}

// ---- transpose fc_w: fcwT[k][j] = fcw[j][k] ----
__global__ void ktrans(const float* __restrict__ fcw) {
    int i = blockIdx.x * 256 + threadIdx.x;   // 32768
    int j = i >> 7, k = i & 127;              // coalesced read
    d_fcwT[k * HF + j] = fcw[i];
}

// ---- convert feat to fp16 (vectorized float4 -> 4 half) ----
__global__ void kcvt(const float* __restrict__ feat, int total4) {
    int i = blockIdx.x * 256 + threadIdx.x;
    if (i < total4) {
        float4 v = ((const float4*)feat)[i];
        uint2 r;
        *(__half2*)&r.x = __floats2half2_rn(v.x, v.y);
        *(__half2*)&r.y = __floats2half2_rn(v.z, v.w);
        ((uint2*)d_feath)[i] = r;
    }
}

// ---- scan A: per-block sums of 256 degrees ----
__global__ void kscanA(int n) {
    __shared__ int sh[256];
    int t = threadIdx.x;
    int i = blockIdx.x * 256 + t;
    sh[t] = (i < n) ? d_deg[i] : 0;
    __syncthreads();
#pragma unroll
    for (int off = 128; off; off >>= 1) {
        if (t < off) sh[t] += sh[t + off];
        __syncthreads();
    }
    if (t == 0) d_bsum[blockIdx.x] = sh[0];
}

// ---- scan B: exclusive scan of block sums (nb <= 256) ----
__global__ void kscanB(int nb, int n, int e) {
    __shared__ int sh[256];
    int t = threadIdx.x;
    sh[t] = (t < nb) ? d_bsum[t] : 0;
    __syncthreads();
#pragma unroll
    for (int off = 1; off < 256; off <<= 1) {
        int x = (t >= off) ? sh[t - off] : 0;
        __syncthreads();
        sh[t] += x;
        __syncthreads();
    }
    if (t < nb) d_bpre[t] = (t ? sh[t - 1] : 0);
    if (t == 0) d_off[n] = e;
}

// ---- scan C: per-block exclusive scan + prefix -> offsets ----
__global__ void kscanC(int n) {
    __shared__ int sh[256];
    int t = threadIdx.x;
    int i = blockIdx.x * 256 + t;
    int v = (i < n) ? d_deg[i] : 0;
    sh[t] = v;
    __syncthreads();
#pragma unroll
    for (int off = 1; off < 256; off <<= 1) {
        int x = (t >= off) ? sh[t - off] : 0;
        __syncthreads();
        sh[t] += x;
        __syncthreads();
    }
    if (i < n) {
        int o = d_bpre[blockIdx.x] + sh[t] - v;  // exclusive
        d_off[i] = o;
        d_cur[i] = o;
    }
}

// ---- K2: per-node el2/er2. One warp per node. ----
__global__ void k2_node(const float* __restrict__ feat, int n) {
    __shared__ float wl[NHEAD * FIN], wr[NHEAD * FIN];
    int t = threadIdx.x;
    wl[t] = d_wl1[t]; wl[t + 256] = d_wl1[t + 256];
    wr[t] = d_wr1[t]; wr[t + 256] = d_wr1[t + 256];
    __syncthreads();
    int warp = t >> 5, lane = t & 31;
    int node = blockIdx.x * 8 + warp;
    if (node >= n) return;

    float4 f = *(const float4*)(feat + (size_t)node * FIN + lane * 4);
    float4 f2 = make_float4(f.x * f.x, f.y * f.y, f.z * f.z, f.w * f.w);
    float accl[4], accr[4];
#pragma unroll
    for (int h = 0; h < 4; h++) {
        const float* a = wl + h * FIN + lane * 4;
        const float* b = wr + h * FIN + lane * 4;
        accl[h] = f2.x * a[0] + f2.y * a[1] + f2.z * a[2] + f2.w * a[3];
        accr[h] = f2.x * b[0] + f2.y * b[1] + f2.z * b[2] + f2.w * b[3];
    }
#pragma unroll
    for (int off = 16; off; off >>= 1) {
#pragma unroll
        for (int h = 0; h < 4; h++) {
            accl[h] += __shfl_xor_sync(0xffffffffu, accl[h], off);
            accr[h] += __shfl_xor_sync(0xffffffffu, accr[h], off);
        }
    }
    if (lane < 4) {
        int idx = node * 4 + lane;
        d_el2[idx] = sel4(accl, lane);
        d_er2[idx] = sel4(accr, lane);
    }
}

// ---- K1: ft = feat @ fc_w^T. k-major smem tiles, 4 LDS.128 / 32 FFMA2. ----
__global__ void __launch_bounds__(256, 2) k1_gemm(const float* __restrict__ feat,
                                                  int n) {
    __shared__ float As[16][68];     // [k][row], pad 68 keeps 16B align
    __shared__ float Bs[16][256];    // [k][j]
    int t = threadIdx.x;
    int tx = t & 31, ty = t >> 5;
    int m0 = blockIdx.x * 64;

    unsigned long long acc2[8][4];
#pragma unroll
    for (int i = 0; i < 8; i++)
#pragma unroll
        for (int j = 0; j < 4; j++) acc2[i][j] = 0ull;

    int arow = t >> 2, akq = (t & 3) * 4;

#pragma unroll
    for (int kc = 0; kc < FIN; kc += 16) {
        // A tile: transpose into [k][row]
        float4 av = make_float4(0.f, 0.f, 0.f, 0.f);
        if (m0 + arow < n)
            av = *(const float4*)(feat + (size_t)(m0 + arow) * FIN + kc + akq);
        As[akq + 0][arow] = av.x;
        As[akq + 1][arow] = av.y;
        As[akq + 2][arow] = av.z;
        As[akq + 3][arow] = av.w;
        // B tile: straight copy from pre-transposed fcwT
#pragma unroll
        for (int i = 0; i < 4; i++) {
            int idx = t + i * 256;            // float4 index in 16x64 grid
            int row = idx >> 6, c4 = (idx & 63) * 4;
            *(float4*)&Bs[row][c4] = *(const float4*)(d_fcwT + (size_t)(kc + row) * HF + c4);
        }
        __syncthreads();

#pragma unroll
        for (int k = 0; k < 16; k++) {
            float4 a0 = *(float4*)&As[k][ty * 8];
            float4 a1 = *(float4*)&As[k][ty * 8 + 4];
            float4 b0 = *(float4*)&Bs[k][tx * 8];
            float4 b1 = *(float4*)&Bs[k][tx * 8 + 4];
            unsigned long long bb0 = pk2(b0.x, b0.y), bb1 = pk2(b0.z, b0.w);
            unsigned long long bb2 = pk2(b1.x, b1.y), bb3 = pk2(b1.z, b1.w);
            float a[8] = {a0.x, a0.y, a0.z, a0.w, a1.x, a1.y, a1.z, a1.w};
#pragma unroll
            for (int i = 0; i < 8; i++) {
                unsigned long long aa = pk2(a[i], a[i]);
                ffma2(acc2[i][0], aa, bb0);
                ffma2(acc2[i][1], aa, bb1);
                ffma2(acc2[i][2], aa, bb2);
                ffma2(acc2[i][3], aa, bb3);
            }
        }
        __syncthreads();
    }

#pragma unroll
    for (int i = 0; i < 8; i++) {
        int row = m0 + ty * 8 + i;
        if (row < n) {
            float v[8];
            upk2(acc2[i][0], v[0], v[1]); upk2(acc2[i][1], v[2], v[3]);
            upk2(acc2[i][2], v[4], v[5]); upk2(acc2[i][3], v[6], v[7]);
            __half2 hv[4];
#pragma unroll
            for (int q = 0; q < 4; q++)
                hv[q] = __floats2half2_rn(v[2 * q], v[2 * q + 1]);
            *(uint4*)(d_fth + (size_t)row * HF + tx * 8) = *(uint4*)hv;
        }
    }
}

// ---- K3: edge scores (fp16 feat) -> exp into CSR. 4 edges/warp, fold-reduce. ----
__global__ void __launch_bounds__(256) k3_edge(const int* __restrict__ src,
                                               const int* __restrict__ dst, int eN) {
    __shared__ float ws[NHEAD * FIN];
    int t = threadIdx.x;
    ws[t] = d_w[t]; ws[t + 256] = d_w[t + 256];
    __syncthreads();
    int warp = t >> 5, lane = t & 31;
    int e0 = (blockIdx.x * 8 + warp) * 4;

    int s[4], d[4];
    bool valid[4];
#pragma unroll
    for (int q = 0; q < 4; q++) {
        int e = e0 + q;
        valid[q] = e < eN;
        s[q] = valid[q] ? src[e] : 0;
        d[q] = valid[q] ? dst[e] : 0;
    }

    float v[16];   // [q*4+h] per-lane partials
#pragma unroll
    for (int q = 0; q < 4; q++) {
        uint2 ua = *(const uint2*)(d_feath + (size_t)s[q] * FIN + lane * 4);
        uint2 ub = *(const uint2*)(d_feath + (size_t)d[q] * FIN + lane * 4);
        float2 pa = __half22float2(__hmul2(*(__half2*)&ua.x, *(__half2*)&ub.x));
        float2 pb = __half22float2(__hmul2(*(__half2*)&ua.y, *(__half2*)&ub.y));
#pragma unroll
        for (int h = 0; h < 4; h++) {
            const float* w4 = ws + h * FIN + lane * 4;
            v[q * 4 + h] = pa.x * w4[0] + pa.y * w4[1] + pb.x * w4[2] + pb.y * w4[3];
        }
    }

    // fold-reduce: 16 values over 32 lanes in 16 shfls
    {
        bool b = (lane & 16) != 0;
#pragma unroll
        for (int i = 0; i < 8; i++) {
            float snd = b ? v[i] : v[i + 8];
            float o = __shfl_xor_sync(0xffffffffu, snd, 16);
            v[i] = (b ? v[i + 8] : v[i]) + o;
        }
        b = (lane & 8) != 0;
#pragma unroll
        for (int i = 0; i < 4; i++) {
            float snd = b ? v[i] : v[i + 4];
            float o = __shfl_xor_sync(0xffffffffu, snd, 8);
            v[i] = (b ? v[i + 4] : v[i]) + o;
        }
        b = (lane & 4) != 0;
#pragma unroll
        for (int i = 0; i < 2; i++) {
            float snd = b ? v[i] : v[i + 2];
            float o = __shfl_xor_sync(0xffffffffu, snd, 4);
            v[i] = (b ? v[i + 2] : v[i]) + o;
        }
        b = (lane & 2) != 0;
        {
            float snd = b ? v[0] : v[1];
            float o = __shfl_xor_sync(0xffffffffu, snd, 2);
            v[0] = (b ? v[1] : v[0]) + o;
        }
        v[0] += __shfl_xor_sync(0xffffffffu, v[0], 1);
    }
    // even lane holds sum for vidx; vidx bits from lane bits 4..1
    int vidx = (((lane >> 4) & 1) << 3) | (((lane >> 3) & 1) << 2)
             | (((lane >> 2) & 1) << 1) | ((lane >> 1) & 1);
    int q = vidx >> 2, h = vidx & 3;

    // CSR slots: lanes 0..3 grab positions for their edge
    int pos = 0;
    if (lane < 4 && valid[lane]) {
        pos = atomicAdd(&d_cur[sel4i(d, lane)], 1);
        d_ssrc[pos] = sel4i(s, lane);
    }
    int pq = __shfl_sync(0xffffffffu, pos, q);

    if (((lane & 1) == 0) && ((e0 + q) < eN)) {
        int sq = sel4i(s, q), dq = sel4i(d, q);
        float sc = v[0] + d_el2[sq * 4 + h] + d_er2[dq * 4 + h];
        d_e[(size_t)h * EMAX + pq] = __expf(sc);   // planar [h][E], max-free
    }
}

// ---- Kdenom: 1/sum(exp) per (node, head). One warp per node, 8 lanes/head. ----
__global__ void kdenom(int n) {
    int gw = (blockIdx.x * 256 + threadIdx.x) >> 5;
    int lane = threadIdx.x & 31;
    if (gw >= n) return;
    int st = d_off[gw], deg = d_off[gw + 1] - st;
    int h = lane >> 3, li = lane & 7;
    float sm = 0.f;
    const float* ep = d_e + (size_t)h * EMAX + st;
    for (int i = li; i < deg; i += 8) sm += ep[i];
#pragma unroll
    for (int off = 4; off; off >>= 1)
        sm += __shfl_xor_sync(0xffffffffu, sm, off);
    if (li == 0) d_inv[gw * 4 + h] = 1.0f / sm;   // inf if deg==0 (never used)
}

// ---- K4: aggregation (fp16 ft, half2/thread). 128 threads, one node/block. ----
__global__ void __launch_bounds__(128) k4_node(float* __restrict__ out,
                                               const float* __restrict__ bias) {
    __shared__ int   srcSm[64];
    __shared__ float alSm[256];   // [h][64] raw exp(e)
    int node = blockIdx.x;
    int t = threadIdx.x;          // covers cols 2t, 2t+1
    int st = d_off[node];
    int deg = d_off[node + 1] - st;

    float2* o2 = (float2*)(out + (size_t)node * HF) + t;
    const float2* b2 = (const float2*)bias + t;
    if (deg == 0) {
        *o2 = *b2;
        return;
    }

    int h = t >> 5;               // head of cols 2t,2t+1
    float inv = d_inv[node * 4 + h];
    float ax = 0.f, ay = 0.f;
    const __half2* fbase = (const __half2*)d_fth;

    for (int c0 = 0; c0 < deg; c0 += 64) {
        int cd = min(64, deg - c0);
        if (t < cd) srcSm[t] = d_ssrc[st + c0 + t];
#pragma unroll
        for (int rr = 0; rr < 2; rr++) {
            int idx = t + rr * 128;           // 0..255
            int hh = idx >> 6, ii = idx & 63;
            if (ii < cd) alSm[idx] = d_e[(size_t)hh * EMAX + st + c0 + ii];
        }
        __syncthreads();
#pragma unroll 8
        for (int i = 0; i < cd; i++) {
            int sId = srcSm[i];
            float2 f = __half22float2(fbase[(size_t)sId * 128 + t]);
            float a = alSm[(h << 6) | i];
            ax = fmaf(a, f.x, ax);
            ay = fmaf(a, f.y, ay);
        }
        __syncthreads();
    }
    float2 bb = *b2;
    float2 r;
    r.x = ax * inv + bb.x;
    r.y = ay * inv + bb.y;
    *o2 = r;
}

extern "C" void kernel_launch(void* const* d_in, const int* in_sizes, int n_in,
                              void* d_out, int out_size) {
    const float* feat = (const float*)d_in[0];
    const int*   src  = (const int*)d_in[1];
    const int*   dst  = (const int*)d_in[2];
    const float* fcw  = (const float*)d_in[3];
    const float* al   = (const float*)d_in[4];
    const float* ar   = (const float*)d_in[5];
    const float* al1  = (const float*)d_in[6];
    const float* ar1  = (const float*)d_in[7];
    const float* bias = (const float*)d_in[8];
    float* out = (float*)d_out;

    int n = in_sizes[0] / FIN;
    int e = in_sizes[1];
    int nb = (n + 255) / 256;
    int t4 = n * FIN / 4;

    kinit<<<nb, 256>>>(al, ar, al1, ar1, n);          // 1
    khist<<<(e + 255) / 256, 256>>>(dst, e);          // 2
    ktrans<<<HF * FIN / 256, 256>>>(fcw);             // 3
    k1_gemm<<<(n + 63) / 64, 256>>>(feat, n);         // 4  <- profiled slot
    kcvt<<<(t4 + 255) / 256, 256>>>(feat, t4);        // 5
    kscanA<<<nb, 256>>>(n);                            // 6
    kscanB<<<1, 256>>>(nb, n, e);                      // 7
    kscanC<<<nb, 256>>>(n);                            // 8
    k2_node<<<(n + 7) / 8, 256>>>(feat, n);            // 9
    k3_edge<<<(e + 31) / 32, 256>>>(src, dst, e);      // 10
    kdenom<<<(n + 7) / 8, 256>>>(n);                   // 11
    k4_node<<<n, 128>>>(out, bias);                    // 12
}

// round 12
// speedup vs baseline: 2.5519x; 1.2006x over previous
#include <cuda_runtime.h>
#include <cuda_fp16.h>
#include <math_constants.h>

#define NMAX 50000
#define EMAX 800000
#define FIN 128
#define NHEAD 4
#define HF 256   // NHEAD * F_OUT

// ---- scratch (device globals; no allocation allowed) ----
__device__ __half d_fth[NMAX * HF];        // projected features [N,256], fp16
__device__ __half d_feath[NMAX * FIN];     // fp16 copy of feat
__device__ __half d_fcwh[HF * FIN];        // fp16 copy of fc_w [n][k]
__device__ float d_e[NHEAD * EMAX];        // exp(edge score), PLANAR [h][E], CSR order
__device__ int   d_ssrc[EMAX];             // src id, CSR order
__device__ int   d_deg[NMAX];              // degree histogram
__device__ int   d_off[NMAX + 1];          // CSR offsets
__device__ int   d_cur[NMAX];              // scatter cursors
__device__ int   d_bsum[256];              // scan block sums
__device__ int   d_bpre[256];              // scan block prefixes
__device__ float d_el2[NMAX * NHEAD];
__device__ float d_er2[NMAX * NHEAD];
__device__ float d_inv[NMAX * NHEAD];      // 1 / softmax denom
__device__ float d_w[NHEAD * FIN];         // al*ar - 2*al1*ar1
__device__ float d_wl1[NHEAD * FIN];       // al1^2
__device__ float d_wr1[NHEAD * FIN];       // ar1^2

__device__ __forceinline__ float sel4(const float a[4], int l) {
    return l == 0 ? a[0] : l == 1 ? a[1] : l == 2 ? a[2] : a[3];
}
__device__ __forceinline__ int sel4i(const int a[4], int l) {
    return l == 0 ? a[0] : l == 1 ? a[1] : l == 2 ? a[2] : a[3];
}

__device__ __forceinline__ unsigned smem_u32(const void* p) {
    unsigned a;
    asm("{ .reg .u64 t; cvta.to.shared.u64 t, %1; cvt.u32.u64 %0, t; }"
        : "=r"(a) : "l"(p));
    return a;
}

// ---- K0: zero degree histogram + combine attention vectors ----
__global__ void kinit(const float* __restrict__ al, const float* __restrict__ ar,
                      const float* __restrict__ al1, const float* __restrict__ ar1, int n) {
    int i = blockIdx.x * 256 + threadIdx.x;
    if (i < n) d_deg[i] = 0;
    if (i < NHEAD * FIN) {
        d_w[i]   = al[i] * ar[i] - 2.0f * al1[i] * ar1[i];
        d_wl1[i] = al1[i] * al1[i];
        d_wr1[i] = ar1[i] * ar1[i];
    }
}

// ---- histogram of dst ----
__global__ void khist(const int* __restrict__ dst, int e) {
    int i = blockIdx.x * blockDim.x + threadIdx.x;
    if (i < e) atomicAdd(&d_deg[dst[i]], 1);
}

// ---- convert feat to fp16 ----
__global__ void kcvt(const float* __restrict__ feat, int total4) {
    int i = blockIdx.x * 256 + threadIdx.x;
    if (i < total4) {
        float4 v = ((const float4*)feat)[i];
        uint2 r;
        *(__half2*)&r.x = __floats2half2_rn(v.x, v.y);
        *(__half2*)&r.y = __floats2half2_rn(v.z, v.w);
        ((uint2*)d_feath)[i] = r;
    }
}

// ---- convert fc_w to fp16 (same [n][k] layout) ----
__global__ void kcvtw(const float* __restrict__ fcw) {
    int i = blockIdx.x * 256 + threadIdx.x;   // total4 = 8192
    if (i < HF * FIN / 4) {
        float4 v = ((const float4*)fcw)[i];
        uint2 r;
        *(__half2*)&r.x = __floats2half2_rn(v.x, v.y);
        *(__half2*)&r.y = __floats2half2_rn(v.z, v.w);
        ((uint2*)d_fcwh)[i] = r;
    }
}

// ---- scan A ----
__global__ void kscanA(int n) {
    __shared__ int sh[256];
    int t = threadIdx.x;
    int i = blockIdx.x * 256 + t;
    sh[t] = (i < n) ? d_deg[i] : 0;
    __syncthreads();
#pragma unroll
    for (int off = 128; off; off >>= 1) {
        if (t < off) sh[t] += sh[t + off];
        __syncthreads();
    }
    if (t == 0) d_bsum[blockIdx.x] = sh[0];
}

// ---- scan B ----
__global__ void kscanB(int nb, int n, int e) {
    __shared__ int sh[256];
    int t = threadIdx.x;
    sh[t] = (t < nb) ? d_bsum[t] : 0;
    __syncthreads();
#pragma unroll
    for (int off = 1; off < 256; off <<= 1) {
        int x = (t >= off) ? sh[t - off] : 0;
        __syncthreads();
        sh[t] += x;
        __syncthreads();
    }
    if (t < nb) d_bpre[t] = (t ? sh[t - 1] : 0);
    if (t == 0) d_off[n] = e;
}

// ---- scan C ----
__global__ void kscanC(int n) {
    __shared__ int sh[256];
    int t = threadIdx.x;
    int i = blockIdx.x * 256 + t;
    int v = (i < n) ? d_deg[i] : 0;
    sh[t] = v;
    __syncthreads();
#pragma unroll
    for (int off = 1; off < 256; off <<= 1) {
        int x = (t >= off) ? sh[t - off] : 0;
        __syncthreads();
        sh[t] += x;
        __syncthreads();
    }
    if (i < n) {
        int o = d_bpre[blockIdx.x] + sh[t] - v;  // exclusive
        d_off[i] = o;
        d_cur[i] = o;
    }
}

// ---- K2: per-node el2/er2. One warp per node. ----
__global__ void k2_node(const float* __restrict__ feat, int n) {
    __shared__ float wl[NHEAD * FIN], wr[NHEAD * FIN];
    int t = threadIdx.x;
    wl[t] = d_wl1[t]; wl[t + 256] = d_wl1[t + 256];
    wr[t] = d_wr1[t]; wr[t + 256] = d_wr1[t + 256];
    __syncthreads();
    int warp = t >> 5, lane = t & 31;
    int node = blockIdx.x * 8 + warp;
    if (node >= n) return;

    float4 f = *(const float4*)(feat + (size_t)node * FIN + lane * 4);
    float4 f2 = make_float4(f.x * f.x, f.y * f.y, f.z * f.z, f.w * f.w);
    float accl[4], accr[4];
#pragma unroll
    for (int h = 0; h < 4; h++) {
        const float* a = wl + h * FIN + lane * 4;
        const float* b = wr + h * FIN + lane * 4;
        accl[h] = f2.x * a[0] + f2.y * a[1] + f2.z * a[2] + f2.w * a[3];
        accr[h] = f2.x * b[0] + f2.y * b[1] + f2.z * b[2] + f2.w * b[3];
    }
#pragma unroll
    for (int off = 16; off; off >>= 1) {
#pragma unroll
        for (int h = 0; h < 4; h++) {
            accl[h] += __shfl_xor_sync(0xffffffffu, accl[h], off);
            accr[h] += __shfl_xor_sync(0xffffffffu, accr[h], off);
        }
    }
    if (lane < 4) {
        int idx = node * 4 + lane;
        d_el2[idx] = sel4(accl, lane);
        d_er2[idx] = sel4(accr, lane);
    }
}

// ---- K1: ft = feat @ fc_w^T via HMMA m16n8k16. Block 32x256, warp 16x64. ----
__global__ void __launch_bounds__(256) k1_mma(int n) {
    __shared__ __half As[32][72];    // k-padded stride 144B
    __shared__ __half Bs[256][72];
    int t = threadIdx.x;
    int lane = t & 31, warp = t >> 5;
    int wm = warp >> 2, wn = warp & 3;   // 2 x 4 warp grid
    int m0 = blockIdx.x * 32;

    float c[8][4];
#pragma unroll
    for (int i = 0; i < 8; i++)
#pragma unroll
        for (int j = 0; j < 4; j++) c[i][j] = 0.f;

    unsigned As_b = smem_u32(&As[0][0]);
    unsigned Bs_b = smem_u32(&Bs[0][0]);

#pragma unroll
    for (int kc = 0; kc < FIN; kc += 64) {
        // load A chunk: 32 rows x 64 halfs
        {
            int row = t >> 3, kq = (t & 7) * 8;
            int gm = m0 + row;
            int gs = (gm < n) ? gm : (n - 1);
            *(uint4*)&As[row][kq] = *(const uint4*)(d_feath + (size_t)gs * FIN + kc + kq);
        }
        // load B chunk: 256 rows(n) x 64 halfs
#pragma unroll
        for (int it = 0; it < 8; it++) {
            int nr = (t >> 3) + it * 32, kq = (t & 7) * 8;
            *(uint4*)&Bs[nr][kq] = *(const uint4*)(d_fcwh + (size_t)nr * FIN + kc + kq);
        }
        __syncthreads();

#pragma unroll
        for (int kk = 0; kk < 64; kk += 16) {
            unsigned a0, a1, a2, a3;
            {
                int r = lane & 15, cq = (lane >> 4) << 3;
                unsigned addr = As_b + ((wm * 16 + r) * 72 + kk + cq) * 2;
                asm volatile("ldmatrix.sync.aligned.m8n8.x4.shared.b16 {%0,%1,%2,%3}, [%4];"
                             : "=r"(a0), "=r"(a1), "=r"(a2), "=r"(a3) : "r"(addr));
            }
#pragma unroll
            for (int nt = 0; nt < 8; nt++) {
                unsigned b0, b1;
                int br = lane & 7, bq = ((lane >> 3) & 1) << 3;
                unsigned addr = Bs_b + ((wn * 64 + nt * 8 + br) * 72 + kk + bq) * 2;
                asm volatile("ldmatrix.sync.aligned.m8n8.x2.shared.b16 {%0,%1}, [%2];"
                             : "=r"(b0), "=r"(b1) : "r"(addr));
                asm volatile("mma.sync.aligned.m16n8k16.row.col.f32.f16.f16.f32 "
                             "{%0,%1,%2,%3}, {%4,%5,%6,%7}, {%8,%9}, {%0,%1,%2,%3};"
                             : "+f"(c[nt][0]), "+f"(c[nt][1]), "+f"(c[nt][2]), "+f"(c[nt][3])
                             : "r"(a0), "r"(a1), "r"(a2), "r"(a3), "r"(b0), "r"(b1));
            }
        }
        __syncthreads();
    }

    // epilogue: fp32 acc -> fp16 d_fth
    int r0 = m0 + wm * 16 + (lane >> 2);
    int cbase = wn * 64 + (lane & 3) * 2;
#pragma unroll
    for (int nt = 0; nt < 8; nt++) {
        int col = cbase + nt * 8;
        if (r0 < n)
            *(__half2*)(d_fth + (size_t)r0 * HF + col) = __floats2half2_rn(c[nt][0], c[nt][1]);
        if (r0 + 8 < n)
            *(__half2*)(d_fth + (size_t)(r0 + 8) * HF + col) = __floats2half2_rn(c[nt][2], c[nt][3]);
    }
}

// ---- K3: edge scores (fp16 feat) -> exp into CSR. 4 edges/warp, fold-reduce. ----
__global__ void __launch_bounds__(256) k3_edge(const int* __restrict__ src,
                                               const int* __restrict__ dst, int eN) {
    __shared__ float ws[NHEAD * FIN];
    int t = threadIdx.x;
    ws[t] = d_w[t]; ws[t + 256] = d_w[t + 256];
    __syncthreads();
    int warp = t >> 5, lane = t & 31;
    int e0 = (blockIdx.x * 8 + warp) * 4;

    int s[4], d[4];
    bool valid[4];
#pragma unroll
    for (int q = 0; q < 4; q++) {
        int e = e0 + q;
        valid[q] = e < eN;
        s[q] = valid[q] ? src[e] : 0;
        d[q] = valid[q] ? dst[e] : 0;
    }

    float v[16];   // [q*4+h] per-lane partials
#pragma unroll
    for (int q = 0; q < 4; q++) {
        uint2 ua = *(const uint2*)(d_feath + (size_t)s[q] * FIN + lane * 4);
        uint2 ub = *(const uint2*)(d_feath + (size_t)d[q] * FIN + lane * 4);
        float2 pa = __half22float2(__hmul2(*(__half2*)&ua.x, *(__half2*)&ub.x));
        float2 pb = __half22float2(__hmul2(*(__half2*)&ua.y, *(__half2*)&ub.y));
#pragma unroll
        for (int h = 0; h < 4; h++) {
            const float* w4 = ws + h * FIN + lane * 4;
            v[q * 4 + h] = pa.x * w4[0] + pa.y * w4[1] + pb.x * w4[2] + pb.y * w4[3];
        }
    }

    // fold-reduce: 16 values over 32 lanes in 16 shfls
    {
        bool b = (lane & 16) != 0;
#pragma unroll
        for (int i = 0; i < 8; i++) {
            float snd = b ? v[i] : v[i + 8];
            float o = __shfl_xor_sync(0xffffffffu, snd, 16);
            v[i] = (b ? v[i + 8] : v[i]) + o;
        }
        b = (lane & 8) != 0;
#pragma unroll
        for (int i = 0; i < 4; i++) {
            float snd = b ? v[i] : v[i + 4];
            float o = __shfl_xor_sync(0xffffffffu, snd, 8);
            v[i] = (b ? v[i + 4] : v[i]) + o;
        }
        b = (lane & 4) != 0;
#pragma unroll
        for (int i = 0; i < 2; i++) {
            float snd = b ? v[i] : v[i + 2];
            float o = __shfl_xor_sync(0xffffffffu, snd, 4);
            v[i] = (b ? v[i + 2] : v[i]) + o;
        }
        b = (lane & 2) != 0;
        {
            float snd = b ? v[0] : v[1];
            float o = __shfl_xor_sync(0xffffffffu, snd, 2);
            v[0] = (b ? v[1] : v[0]) + o;
        }
        v[0] += __shfl_xor_sync(0xffffffffu, v[0], 1);
    }
    int vidx = (((lane >> 4) & 1) << 3) | (((lane >> 3) & 1) << 2)
             | (((lane >> 2) & 1) << 1) | ((lane >> 1) & 1);
    int q = vidx >> 2, h = vidx & 3;

    int pos = 0;
    if (lane < 4 && valid[lane]) {
        pos = atomicAdd(&d_cur[sel4i(d, lane)], 1);
        d_ssrc[pos] = sel4i(s, lane);
    }
    int pq = __shfl_sync(0xffffffffu, pos, q);

    if (((lane & 1) == 0) && ((e0 + q) < eN)) {
        int sq = sel4i(s, q), dq = sel4i(d, q);
        float sc = v[0] + d_el2[sq * 4 + h] + d_er2[dq * 4 + h];
        d_e[(size_t)h * EMAX + pq] = __expf(sc);   // planar [h][E], max-free
    }
}

// ---- Kdenom: 1/sum(exp) per (node, head). One warp per node, 8 lanes/head. ----
__global__ void kdenom(int n) {
    int gw = (blockIdx.x * 256 + threadIdx.x) >> 5;
    int lane = threadIdx.x & 31;
    if (gw >= n) return;
    int st = d_off[gw], deg = d_off[gw + 1] - st;
    int h = lane >> 3, li = lane & 7;
    float sm = 0.f;
    const float* ep = d_e + (size_t)h * EMAX + st;
    for (int i = li; i < deg; i += 8) sm += ep[i];
#pragma unroll
    for (int off = 4; off; off >>= 1)
        sm += __shfl_xor_sync(0xffffffffu, sm, off);
    if (li == 0) d_inv[gw * 4 + h] = 1.0f / sm;
}

// ---- K4: aggregation (fp16 ft, half2/thread). 128 threads, one node/block. ----
__global__ void __launch_bounds__(128) k4_node(float* __restrict__ out,
                                               const float* __restrict__ bias) {
    __shared__ int   srcSm[64];
    __shared__ float alSm[256];   // [h][64] raw exp(e)
    int node = blockIdx.x;
    int t = threadIdx.x;          // covers cols 2t, 2t+1
    int st = d_off[node];
    int deg = d_off[node + 1] - st;

    float2* o2 = (float2*)(out + (size_t)node * HF) + t;
    const float2* b2 = (const float2*)bias + t;
    if (deg == 0) {
        *o2 = *b2;
        return;
    }

    int h = t >> 5;
    float inv = d_inv[node * 4 + h];
    float ax = 0.f, ay = 0.f;
    const __half2* fbase = (const __half2*)d_fth;

    for (int c0 = 0; c0 < deg; c0 += 64) {
        int cd = min(64, deg - c0);
        if (t < cd) srcSm[t] = d_ssrc[st + c0 + t];
#pragma unroll
        for (int rr = 0; rr < 2; rr++) {
            int idx = t + rr * 128;
            int hh = idx >> 6, ii = idx & 63;
            if (ii < cd) alSm[idx] = d_e[(size_t)hh * EMAX + st + c0 + ii];
        }
        __syncthreads();
#pragma unroll 8
        for (int i = 0; i < cd; i++) {
            int sId = srcSm[i];
            float2 f = __half22float2(fbase[(size_t)sId * 128 + t]);
            float a = alSm[(h << 6) | i];
            ax = fmaf(a, f.x, ax);
            ay = fmaf(a, f.y, ay);
        }
        __syncthreads();
    }
    float2 bb = *b2;
    float2 r;
    r.x = ax * inv + bb.x;
    r.y = ay * inv + bb.y;
    *o2 = r;
}

extern "C" void kernel_launch(void* const* d_in, const int* in_sizes, int n_in,
                              void* d_out, int out_size) {
    const float* feat = (const float*)d_in[0];
    const int*   src  = (const int*)d_in[1];
    const int*   dst  = (const int*)d_in[2];
    const float* fcw  = (const float*)d_in[3];
    const float* al   = (const float*)d_in[4];
    const float* ar   = (const float*)d_in[5];
    const float* al1  = (const float*)d_in[6];
    const float* ar1  = (const float*)d_in[7];
    const float* bias = (const float*)d_in[8];
    float* out = (float*)d_out;

    int n = in_sizes[0] / FIN;
    int e = in_sizes[1];
    int nb = (n + 255) / 256;
    int t4 = n * FIN / 4;

    kinit<<<nb, 256>>>(al, ar, al1, ar1, n);          // 1
    kcvt<<<(t4 + 255) / 256, 256>>>(feat, t4);        // 2
    kcvtw<<<HF * FIN / 4 / 256, 256>>>(fcw);          // 3
    k1_mma<<<(n + 31) / 32, 256>>>(n);                // 4  <- profiled slot
    khist<<<(e + 255) / 256, 256>>>(dst, e);          // 5
    kscanA<<<nb, 256>>>(n);                            // 6
    kscanB<<<1, 256>>>(nb, n, e);                      // 7
    kscanC<<<nb, 256>>>(n);                            // 8
    k2_node<<<(n + 7) / 8, 256>>>(feat, n);            // 9
    k3_edge<<<(e + 31) / 32, 256>>>(src, dst, e);      // 10
    kdenom<<<(n + 7) / 8, 256>>>(n);                   // 11
    k4_node<<<n, 128>>>(out, bias);                    // 12
}

// round 14
// speedup vs baseline: 2.9557x; 1.1582x over previous
#include <cuda_runtime.h>
#include <cuda_fp16.h>
#include <math_constants.h>

#define NMAX 50000
#define EMAX 800000
#define FIN 128
#define NHEAD 4
#define HF 256   // NHEAD * F_OUT

// ---- scratch (device globals; no allocation allowed) ----
__device__ __half d_fth[NMAX * HF];        // projected features [N,256], fp16
__device__ __half d_feath[NMAX * FIN];     // fp16 copy of feat
__device__ __half d_fcwh[HF * FIN];        // fp16 copy of fc_w [n][k]
__device__ float d_e[NHEAD * EMAX];        // exp(edge score), PLANAR [h][E], CSR order
__device__ int   d_ssrc[EMAX];             // src id, CSR order
__device__ int   d_deg[NMAX];              // degree histogram
__device__ int   d_off[NMAX + 1];          // CSR offsets
__device__ int   d_cur[NMAX];              // scatter cursors
__device__ int   d_bsum[256];              // scan block sums
__device__ int   d_bpre[256];              // scan block prefixes
__device__ float d_el2[NMAX * NHEAD];
__device__ float d_er2[NMAX * NHEAD];
__device__ float d_inv[NMAX * NHEAD];      // 1 / softmax denom
__device__ float d_w[NHEAD * FIN];         // al*ar - 2*al1*ar1
__device__ float d_wl1[NHEAD * FIN];       // al1^2
__device__ float d_wr1[NHEAD * FIN];       // ar1^2

__device__ __forceinline__ float sel4(const float a[4], int l) {
    return l == 0 ? a[0] : l == 1 ? a[1] : l == 2 ? a[2] : a[3];
}
__device__ __forceinline__ int sel8i(const int a[8], int l) {
    int x0 = (l & 1) ? a[1] : a[0];
    int x1 = (l & 1) ? a[3] : a[2];
    int x2 = (l & 1) ? a[5] : a[4];
    int x3 = (l & 1) ? a[7] : a[6];
    int y0 = (l & 2) ? x1 : x0;
    int y1 = (l & 2) ? x3 : x2;
    return (l & 4) ? y1 : y0;
}

__device__ __forceinline__ unsigned smem_u32(const void* p) {
    unsigned a;
    asm("{ .reg .u64 t; cvta.to.shared.u64 t, %1; cvt.u32.u64 %0, t; }"
        : "=r"(a) : "l"(p));
    return a;
}

// ---- K0: zero degree histogram + combine attention vectors ----
__global__ void kinit(const float* __restrict__ al, const float* __restrict__ ar,
                      const float* __restrict__ al1, const float* __restrict__ ar1, int n) {
    int i = blockIdx.x * 256 + threadIdx.x;
    if (i < n) d_deg[i] = 0;
    if (i < NHEAD * FIN) {
        d_w[i]   = al[i] * ar[i] - 2.0f * al1[i] * ar1[i];
        d_wl1[i] = al1[i] * al1[i];
        d_wr1[i] = ar1[i] * ar1[i];
    }
}

// ---- histogram of dst ----
__global__ void khist(const int* __restrict__ dst, int e) {
    int i = blockIdx.x * blockDim.x + threadIdx.x;
    if (i < e) atomicAdd(&d_deg[dst[i]], 1);
}

// ---- convert feat to fp16 ----
__global__ void kcvt(const float* __restrict__ feat, int total4) {
    int i = blockIdx.x * 256 + threadIdx.x;
    if (i < total4) {
        float4 v = ((const float4*)feat)[i];
        uint2 r;
        *(__half2*)&r.x = __floats2half2_rn(v.x, v.y);
        *(__half2*)&r.y = __floats2half2_rn(v.z, v.w);
        ((uint2*)d_feath)[i] = r;
    }
}

// ---- convert fc_w to fp16 (same [n][k] layout) ----
__global__ void kcvtw(const float* __restrict__ fcw) {
    int i = blockIdx.x * 256 + threadIdx.x;   // total4 = 8192
    if (i < HF * FIN / 4) {
        float4 v = ((const float4*)fcw)[i];
        uint2 r;
        *(__half2*)&r.x = __floats2half2_rn(v.x, v.y);
        *(__half2*)&r.y = __floats2half2_rn(v.z, v.w);
        ((uint2*)d_fcwh)[i] = r;
    }
}

// ---- scan A ----
__global__ void kscanA(int n) {
    __shared__ int sh[256];
    int t = threadIdx.x;
    int i = blockIdx.x * 256 + t;
    sh[t] = (i < n) ? d_deg[i] : 0;
    __syncthreads();
#pragma unroll
    for (int off = 128; off; off >>= 1) {
        if (t < off) sh[t] += sh[t + off];
        __syncthreads();
    }
    if (t == 0) d_bsum[blockIdx.x] = sh[0];
}

// ---- scan B ----
__global__ void kscanB(int nb, int n, int e) {
    __shared__ int sh[256];
    int t = threadIdx.x;
    sh[t] = (t < nb) ? d_bsum[t] : 0;
    __syncthreads();
#pragma unroll
    for (int off = 1; off < 256; off <<= 1) {
        int x = (t >= off) ? sh[t - off] : 0;
        __syncthreads();
        sh[t] += x;
        __syncthreads();
    }
    if (t < nb) d_bpre[t] = (t ? sh[t - 1] : 0);
    if (t == 0) d_off[n] = e;
}

// ---- scan C ----
__global__ void kscanC(int n) {
    __shared__ int sh[256];
    int t = threadIdx.x;
    int i = blockIdx.x * 256 + t;
    int v = (i < n) ? d_deg[i] : 0;
    sh[t] = v;
    __syncthreads();
#pragma unroll
    for (int off = 1; off < 256; off <<= 1) {
        int x = (t >= off) ? sh[t - off] : 0;
        __syncthreads();
        sh[t] += x;
        __syncthreads();
    }
    if (i < n) {
        int o = d_bpre[blockIdx.x] + sh[t] - v;  // exclusive
        d_off[i] = o;
        d_cur[i] = o;
    }
}

// ---- K2: per-node el2/er2. One warp per node. ----
__global__ void k2_node(const float* __restrict__ feat, int n) {
    __shared__ float wl[NHEAD * FIN], wr[NHEAD * FIN];
    int t = threadIdx.x;
    wl[t] = d_wl1[t]; wl[t + 256] = d_wl1[t + 256];
    wr[t] = d_wr1[t]; wr[t + 256] = d_wr1[t + 256];
    __syncthreads();
    int warp = t >> 5, lane = t & 31;
    int node = blockIdx.x * 8 + warp;
    if (node >= n) return;

    float4 f = *(const float4*)(feat + (size_t)node * FIN + lane * 4);
    float4 f2 = make_float4(f.x * f.x, f.y * f.y, f.z * f.z, f.w * f.w);
    float accl[4], accr[4];
#pragma unroll
    for (int h = 0; h < 4; h++) {
        const float* a = wl + h * FIN + lane * 4;
        const float* b = wr + h * FIN + lane * 4;
        accl[h] = f2.x * a[0] + f2.y * a[1] + f2.z * a[2] + f2.w * a[3];
        accr[h] = f2.x * b[0] + f2.y * b[1] + f2.z * b[2] + f2.w * b[3];
    }
#pragma unroll
    for (int off = 16; off; off >>= 1) {
#pragma unroll
        for (int h = 0; h < 4; h++) {
            accl[h] += __shfl_xor_sync(0xffffffffu, accl[h], off);
            accr[h] += __shfl_xor_sync(0xffffffffu, accr[h], off);
        }
    }
    if (lane < 4) {
        int idx = node * 4 + lane;
        d_el2[idx] = sel4(accl, lane);
        d_er2[idx] = sel4(accr, lane);
    }
}

// ---- K1: ft = feat @ fc_w^T via HMMA m16n8k16. Block 32x256, warp 16x64. ----
__global__ void __launch_bounds__(256) k1_mma(int n) {
    __shared__ __half As[32][72];
    __shared__ __half Bs[256][72];
    int t = threadIdx.x;
    int lane = t & 31, warp = t >> 5;
    int wm = warp >> 2, wn = warp & 3;
    int m0 = blockIdx.x * 32;

    float c[8][4];
#pragma unroll
    for (int i = 0; i < 8; i++)
#pragma unroll
        for (int j = 0; j < 4; j++) c[i][j] = 0.f;

    unsigned As_b = smem_u32(&As[0][0]);
    unsigned Bs_b = smem_u32(&Bs[0][0]);

#pragma unroll
    for (int kc = 0; kc < FIN; kc += 64) {
        {
            int row = t >> 3, kq = (t & 7) * 8;
            int gm = m0 + row;
            int gs = (gm < n) ? gm : (n - 1);
            *(uint4*)&As[row][kq] = *(const uint4*)(d_feath + (size_t)gs * FIN + kc + kq);
        }
#pragma unroll
        for (int it = 0; it < 8; it++) {
            int nr = (t >> 3) + it * 32, kq = (t & 7) * 8;
            *(uint4*)&Bs[nr][kq] = *(const uint4*)(d_fcwh + (size_t)nr * FIN + kc + kq);
        }
        __syncthreads();

#pragma unroll
        for (int kk = 0; kk < 64; kk += 16) {
            unsigned a0, a1, a2, a3;
            {
                int r = lane & 15, cq = (lane >> 4) << 3;
                unsigned addr = As_b + ((wm * 16 + r) * 72 + kk + cq) * 2;
                asm volatile("ldmatrix.sync.aligned.m8n8.x4.shared.b16 {%0,%1,%2,%3}, [%4];"
                             : "=r"(a0), "=r"(a1), "=r"(a2), "=r"(a3) : "r"(addr));
            }
#pragma unroll
            for (int nt = 0; nt < 8; nt++) {
                unsigned b0, b1;
                int br = lane & 7, bq = ((lane >> 3) & 1) << 3;
                unsigned addr = Bs_b + ((wn * 64 + nt * 8 + br) * 72 + kk + bq) * 2;
                asm volatile("ldmatrix.sync.aligned.m8n8.x2.shared.b16 {%0,%1}, [%2];"
                             : "=r"(b0), "=r"(b1) : "r"(addr));
                asm volatile("mma.sync.aligned.m16n8k16.row.col.f32.f16.f16.f32 "
                             "{%0,%1,%2,%3}, {%4,%5,%6,%7}, {%8,%9}, {%0,%1,%2,%3};"
                             : "+f"(c[nt][0]), "+f"(c[nt][1]), "+f"(c[nt][2]), "+f"(c[nt][3])
                             : "r"(a0), "r"(a1), "r"(a2), "r"(a3), "r"(b0), "r"(b1));
            }
        }
        __syncthreads();
    }

    int r0 = m0 + wm * 16 + (lane >> 2);
    int cbase = wn * 64 + (lane & 3) * 2;
#pragma unroll
    for (int nt = 0; nt < 8; nt++) {
        int col = cbase + nt * 8;
        if (r0 < n)
            *(__half2*)(d_fth + (size_t)r0 * HF + col) = __floats2half2_rn(c[nt][0], c[nt][1]);
        if (r0 + 8 < n)
            *(__half2*)(d_fth + (size_t)(r0 + 8) * HF + col) = __floats2half2_rn(c[nt][2], c[nt][3]);
    }
}

// ---- K3: edge scores -> exp into CSR. 8 edges/warp, 32-value full fold. ----
__global__ void __launch_bounds__(256) k3_edge(const int* __restrict__ src,
                                               const int* __restrict__ dst, int eN) {
    __shared__ float ws[NHEAD * FIN];
    int t = threadIdx.x;
    ws[t] = d_w[t]; ws[t + 256] = d_w[t + 256];
    __syncthreads();
    int warp = t >> 5, lane = t & 31;
    int e0 = (blockIdx.x * 8 + warp) * 8;

    int s[8], d[8];
#pragma unroll
    for (int q = 0; q < 8; q++) {
        int e = e0 + q;
        bool val = e < eN;
        s[q] = val ? src[e] : 0;
        d[q] = val ? dst[e] : 0;
    }

    float v[32];   // [q*4+h] per-lane partials
#pragma unroll
    for (int q = 0; q < 8; q++) {
        uint2 ua = *(const uint2*)(d_feath + (size_t)s[q] * FIN + lane * 4);
        uint2 ub = *(const uint2*)(d_feath + (size_t)d[q] * FIN + lane * 4);
        float2 pa = __half22float2(__hmul2(*(__half2*)&ua.x, *(__half2*)&ub.x));
        float2 pb = __half22float2(__hmul2(*(__half2*)&ua.y, *(__half2*)&ub.y));
#pragma unroll
        for (int h = 0; h < 4; h++) {
            const float* w4 = ws + h * FIN + lane * 4;
            v[q * 4 + h] = pa.x * w4[0] + pa.y * w4[1] + pb.x * w4[2] + pb.y * w4[3];
        }
    }

    // full fold: 32 values over 32 lanes in 31 shfls; lane L ends with value L
    {
        bool b = (lane & 16) != 0;
#pragma unroll
        for (int i = 0; i < 16; i++) {
            float snd = b ? v[i] : v[i + 16];
            float o = __shfl_xor_sync(0xffffffffu, snd, 16);
            v[i] = (b ? v[i + 16] : v[i]) + o;
        }
        b = (lane & 8) != 0;
#pragma unroll
        for (int i = 0; i < 8; i++) {
            float snd = b ? v[i] : v[i + 8];
            float o = __shfl_xor_sync(0xffffffffu, snd, 8);
            v[i] = (b ? v[i + 8] : v[i]) + o;
        }
        b = (lane & 4) != 0;
#pragma unroll
        for (int i = 0; i < 4; i++) {
            float snd = b ? v[i] : v[i + 4];
            float o = __shfl_xor_sync(0xffffffffu, snd, 4);
            v[i] = (b ? v[i + 4] : v[i]) + o;
        }
        b = (lane & 2) != 0;
#pragma unroll
        for (int i = 0; i < 2; i++) {
            float snd = b ? v[i] : v[i + 2];
            float o = __shfl_xor_sync(0xffffffffu, snd, 2);
            v[i] = (b ? v[i + 2] : v[i]) + o;
        }
        b = (lane & 1) != 0;
        {
            float snd = b ? v[0] : v[1];
            float o = __shfl_xor_sync(0xffffffffu, snd, 1);
            v[0] = (b ? v[1] : v[0]) + o;
        }
    }
    int q = lane >> 2, h = lane & 3;   // lane L owns value L = q*4+h

    // CSR slots: lanes 0..7 grab positions for edges 0..7 (one atomic instr)
    int pos = 0;
    if (lane < 8 && (e0 + lane) < eN) {
        pos = atomicAdd(&d_cur[sel8i(d, lane)], 1);
        d_ssrc[pos] = sel8i(s, lane);
    }
    int pq = __shfl_sync(0xffffffffu, pos, q);

    if ((e0 + q) < eN) {
        int sq = sel8i(s, q), dq = sel8i(d, q);
        float sc = v[0] + d_el2[sq * 4 + h] + d_er2[dq * 4 + h];
        d_e[(size_t)h * EMAX + pq] = __expf(sc);   // planar [h][E], max-free
    }
}

// ---- Kdenom: 1/sum(exp) per (node, head). One warp per node, 8 lanes/head. ----
__global__ void kdenom(int n) {
    int gw = (blockIdx.x * 256 + threadIdx.x) >> 5;
    int lane = threadIdx.x & 31;
    if (gw >= n) return;
    int st = d_off[gw], deg = d_off[gw + 1] - st;
    int h = lane >> 3, li = lane & 7;
    float sm = 0.f;
    const float* ep = d_e + (size_t)h * EMAX + st;
    for (int i = li; i < deg; i += 8) sm += ep[i];
#pragma unroll
    for (int off = 4; off; off >>= 1)
        sm += __shfl_xor_sync(0xffffffffu, sm, off);
    if (li == 0) d_inv[gw * 4 + h] = 1.0f / sm;
}

// ---- K4: aggregation (fp16 ft, half2/thread). 128 threads, one node/block. ----
__global__ void __launch_bounds__(128) k4_node(float* __restrict__ out,
                                               const float* __restrict__ bias) {
    __shared__ int   srcSm[64];
    __shared__ float alSm[256];   // [h][64] raw exp(e)
    int node = blockIdx.x;
    int t = threadIdx.x;          // covers cols 2t, 2t+1
    int st = d_off[node];
    int deg = d_off[node + 1] - st;

    float2* o2 = (float2*)(out + (size_t)node * HF) + t;
    const float2* b2 = (const float2*)bias + t;
    if (deg == 0) {
        *o2 = *b2;
        return;
    }

    int h = t >> 5;
    float inv = d_inv[node * 4 + h];
    float ax = 0.f, ay = 0.f;
    const __half2* fbase = (const __half2*)d_fth;

    for (int c0 = 0; c0 < deg; c0 += 64) {
        int cd = min(64, deg - c0);
        if (t < cd) srcSm[t] = d_ssrc[st + c0 + t];
#pragma unroll
        for (int rr = 0; rr < 2; rr++) {
            int idx = t + rr * 128;
            int hh = idx >> 6, ii = idx & 63;
            if (ii < cd) alSm[idx] = d_e[(size_t)hh * EMAX + st + c0 + ii];
        }
        __syncthreads();
#pragma unroll 8
        for (int i = 0; i < cd; i++) {
            int sId = srcSm[i];
            float2 f = __half22float2(fbase[(size_t)sId * 128 + t]);
            float a = alSm[(h << 6) | i];
            ax = fmaf(a, f.x, ax);
            ay = fmaf(a, f.y, ay);
        }
        __syncthreads();
    }
    float2 bb = *b2;
    float2 r;
    r.x = ax * inv + bb.x;
    r.y = ay * inv + bb.y;
    *o2 = r;
}

extern "C" void kernel_launch(void* const* d_in, const int* in_sizes, int n_in,
                              void* d_out, int out_size) {
    const float* feat = (const float*)d_in[0];
    const int*   src  = (const int*)d_in[1];
    const int*   dst  = (const int*)d_in[2];
    const float* fcw  = (const float*)d_in[3];
    const float* al   = (const float*)d_in[4];
    const float* ar   = (const float*)d_in[5];
    const float* al1  = (const float*)d_in[6];
    const float* ar1  = (const float*)d_in[7];
    const float* bias = (const float*)d_in[8];
    float* out = (float*)d_out;

    int n = in_sizes[0] / FIN;
    int e = in_sizes[1];
    int nb = (n + 255) / 256;
    int t4 = n * FIN / 4;

    // one-time side streams/events for graph fork-join (no device memory)
    static cudaStream_t sB = nullptr, sC = nullptr;
    static cudaEvent_t evF = nullptr, evB = nullptr, evC = nullptr, evF2 = nullptr;
    if (sB == nullptr) {
        cudaStreamCreateWithFlags(&sB, cudaStreamNonBlocking);
        cudaStreamCreateWithFlags(&sC, cudaStreamNonBlocking);
        cudaEventCreateWithFlags(&evF, cudaEventDisableTiming);
        cudaEventCreateWithFlags(&evB, cudaEventDisableTiming);
        cudaEventCreateWithFlags(&evC, cudaEventDisableTiming);
        cudaEventCreateWithFlags(&evF2, cudaEventDisableTiming);
    }

    kinit<<<nb, 256>>>(al, ar, al1, ar1, n);
    cudaEventRecord(evF, 0);

    // branch B: histogram + scans (needs only kinit)
    cudaStreamWaitEvent(sB, evF, 0);
    khist<<<(e + 255) / 256, 256, 0, sB>>>(dst, e);
    kscanA<<<nb, 256, 0, sB>>>(n);
    kscanB<<<1, 256, 0, sB>>>(nb, n, e);
    kscanC<<<nb, 256, 0, sB>>>(n);
    cudaEventRecord(evB, sB);

    // main: conversions + node terms
    kcvt<<<(t4 + 255) / 256, 256>>>(feat, t4);
    kcvtw<<<HF * FIN / 4 / 256, 256>>>(fcw);
    cudaEventRecord(evF2, 0);

    // branch C: GEMM (needed only by k4)
    cudaStreamWaitEvent(sC, evF2, 0);
    k1_mma<<<(n + 31) / 32, 256, 0, sC>>>(n);
    cudaEventRecord(evC, sC);

    k2_node<<<(n + 7) / 8, 256>>>(feat, n);

    // join B, then edge scoring
    cudaStreamWaitEvent(0, evB, 0);
    k3_edge<<<(e + 63) / 64, 256>>>(src, dst, e);
    kdenom<<<(n + 7) / 8, 256>>>(n);

    // join C, then aggregation
    cudaStreamWaitEvent(0, evC, 0);
    k4_node<<<n, 128>>>(out, bias);
}